// round 6
// baseline (speedup 1.0000x reference)
#include <cuda_runtime.h>

// ---------------------------------------------------------------------------
// Problem constants
// ---------------------------------------------------------------------------
#define BB    4
#define NSEQ  2048
#define MSEQ  512
#define HH    12
#define DD    64
#define DIMV  768
#define TRIPLE 2304
#define BH    (BB*HH)          // 48
#define SCALEF 0.125f
#define TEMPF  24.0f
#define NEGF  (-1e9f)

// Output segment offsets (floats)
#define OUT1_OFF 0
#define OUT2_OFF (BB*NSEQ*DIMV)                 // 6291456
#define OUT3_OFF (OUT2_OFF + BB*MSEQ*DIMV)      // 7864320
#define OUT4_OFF (OUT3_OFF + BB*DIMV)           // 7867392

// ---------------------------------------------------------------------------
// Packed f32x2 helpers (FFMA2 — only reachable via PTX)
// ---------------------------------------------------------------------------
#define FMA_X2(d, a, b, c) \
    asm("fma.rn.f32x2 %0, %1, %2, %3;" : "=l"(d) : "l"(a), "l"(b), "l"(c))
#define PACK_DUP(p, f) \
    asm("mov.b64 %0, {%1, %2};" : "=l"(p) : "f"(f), "f"(f))
#define UNPACK_X2(lo, hi, p) \
    asm("mov.b64 {%0, %1}, %2;" : "=f"(lo), "=f"(hi) : "l"(p))

typedef unsigned long long u64t;

// ---------------------------------------------------------------------------
// Device scratch (no cudaMalloc allowed)
// ---------------------------------------------------------------------------
__device__ float g_tq[BB*HH*NSEQ*DD];
__device__ float g_tk[BB*HH*NSEQ*DD];
__device__ float g_tv[BB*HH*NSEQ*DD];
__device__ float g_kq[BB*HH*MSEQ*DD];
__device__ float g_kk[BB*HH*MSEQ*DD];
__device__ float g_kv[BB*HH*MSEQ*DD];
__device__ float g_cq[BB*HH*DD];
__device__ float g_ck[BB*HH*DD];
__device__ float g_cv[BB*HH*DD];
__device__ float g_dots1[BB*HH*NSEQ*MSEQ];   // later overwritten with attn
__device__ float g_dots2[BB*HH*MSEQ*NSEQ];   // later overwritten with k_attn
__device__ float g_attO[BB*NSEQ*DIMV];
__device__ float g_kO[BB*MSEQ*DIMV];
__device__ float g_cO[BB*DIMV];
__device__ float g_mx1[BB*HH*NSEQ];
__device__ float g_s1 [BB*HH*NSEQ];
__device__ float g_sh1[BB*HH*NSEQ];

// ---------------------------------------------------------------------------
// QKV GEMM:  C[rows,2304] = A[rows,768] @ W[768,2304], scatter to q/k/v
// f32x2 inner loop + global->reg prefetch pipeline; 2 CTAs/SM enforced
// ---------------------------------------------------------------------------
__global__ void __launch_bounds__(256, 2) qkv_gemm(
    const float* __restrict__ A, const float* __restrict__ W,
    float* __restrict__ oq, float* __restrict__ ok2, float* __restrict__ ov,
    int rows, int seq)
{
    __shared__ float As[16][132];
    __shared__ float Bs[16][132];
    int tid = threadIdx.x;
    int rowBase = blockIdx.y * 128;
    int colBase = blockIdx.x * 128;
    int trow = tid >> 4, tcol = tid & 15;
    u64t acc[8][4];
#pragma unroll
    for (int i = 0; i < 8; i++)
#pragma unroll
        for (int j = 0; j < 4; j++) acc[i][j] = 0ull;

    int aRow = tid >> 2, aCol = (tid & 3) << 2;
    int bRow = tid >> 5, bCol = (tid & 31) << 2;

    float4 aReg[2], bReg[2];
    // prefetch kk = 0
#pragma unroll
    for (int it = 0; it < 2; ++it) {
        int r = rowBase + aRow + it * 64;
        aReg[it] = make_float4(0.f, 0.f, 0.f, 0.f);
        if (r < rows) aReg[it] = *(const float4*)(A + (size_t)r * DIMV + aCol);
        bReg[it] = *(const float4*)(W + (size_t)(bRow + it * 8) * TRIPLE + colBase + bCol);
    }

    for (int kk = 0; kk < DIMV; kk += 16) {
        // store staged regs to smem
#pragma unroll
        for (int it = 0; it < 2; ++it) {
            As[aCol + 0][aRow + it * 64] = aReg[it].x;
            As[aCol + 1][aRow + it * 64] = aReg[it].y;
            As[aCol + 2][aRow + it * 64] = aReg[it].z;
            As[aCol + 3][aRow + it * 64] = aReg[it].w;
            *(float4*)&Bs[bRow + it * 8][bCol] = bReg[it];
        }
        __syncthreads();
        // prefetch next tile
        if (kk + 16 < DIMV) {
#pragma unroll
            for (int it = 0; it < 2; ++it) {
                int r = rowBase + aRow + it * 64;
                aReg[it] = make_float4(0.f, 0.f, 0.f, 0.f);
                if (r < rows) aReg[it] = *(const float4*)(A + (size_t)r * DIMV + kk + 16 + aCol);
                bReg[it] = *(const float4*)(W + (size_t)(kk + 16 + bRow + it * 8) * TRIPLE + colBase + bCol);
            }
        }
#pragma unroll
        for (int k = 0; k < 16; k++) {
            u64t rbp[4];
#pragma unroll
            for (int j = 0; j < 4; j++)
                rbp[j] = *(const u64t*)&Bs[k][tcol * 8 + 2 * j];
#pragma unroll
            for (int i = 0; i < 8; i++) {
                float a = As[k][trow * 8 + i];
                u64t ap; PACK_DUP(ap, a);
#pragma unroll
                for (int j = 0; j < 4; j++) FMA_X2(acc[i][j], ap, rbp[j], acc[i][j]);
            }
        }
        __syncthreads();
    }

#pragma unroll
    for (int i = 0; i < 8; i++) {
        int r = rowBase + trow * 8 + i;
        if (r >= rows) break;
        int b = r / seq, s = r % seq;
#pragma unroll
        for (int j = 0; j < 4; j++) {
            float v0, v1;
            UNPACK_X2(v0, v1, acc[i][j]);
#pragma unroll
            for (int u = 0; u < 2; u++) {
                int c = colBase + tcol * 8 + 2 * j + u;
                float v = u ? v1 : v0;
                int part = c / DIMV, cc = c % DIMV;
                int h = cc >> 6, d = cc & 63;
                int idx = ((b * HH + h) * seq + s) * DD + d;
                if (part == 0) oq[idx] = v;
                else if (part == 1) ok2[idx] = v;
                else ov[idx] = v;
            }
        }
    }
}

// ---------------------------------------------------------------------------
// Projection GEMM: out[rows,768] = A[rows,768] @ W[768,768] + bias
// ---------------------------------------------------------------------------
__global__ void __launch_bounds__(256, 2) proj_gemm(
    const float* __restrict__ A, const float* __restrict__ W,
    const float* __restrict__ bias, float* __restrict__ outp, int rows)
{
    __shared__ float As[16][132];
    __shared__ float Bs[16][132];
    int tid = threadIdx.x;
    int rowBase = blockIdx.y * 128;
    int colBase = blockIdx.x * 128;
    int trow = tid >> 4, tcol = tid & 15;
    u64t acc[8][4];
#pragma unroll
    for (int i = 0; i < 8; i++)
#pragma unroll
        for (int j = 0; j < 4; j++) acc[i][j] = 0ull;

    int aRow = tid >> 2, aCol = (tid & 3) << 2;
    int bRow = tid >> 5, bCol = (tid & 31) << 2;

    float4 aReg[2], bReg[2];
#pragma unroll
    for (int it = 0; it < 2; ++it) {
        int r = rowBase + aRow + it * 64;
        aReg[it] = make_float4(0.f, 0.f, 0.f, 0.f);
        if (r < rows) aReg[it] = *(const float4*)(A + (size_t)r * DIMV + aCol);
        bReg[it] = *(const float4*)(W + (size_t)(bRow + it * 8) * DIMV + colBase + bCol);
    }

    for (int kk = 0; kk < DIMV; kk += 16) {
#pragma unroll
        for (int it = 0; it < 2; ++it) {
            As[aCol + 0][aRow + it * 64] = aReg[it].x;
            As[aCol + 1][aRow + it * 64] = aReg[it].y;
            As[aCol + 2][aRow + it * 64] = aReg[it].z;
            As[aCol + 3][aRow + it * 64] = aReg[it].w;
            *(float4*)&Bs[bRow + it * 8][bCol] = bReg[it];
        }
        __syncthreads();
        if (kk + 16 < DIMV) {
#pragma unroll
            for (int it = 0; it < 2; ++it) {
                int r = rowBase + aRow + it * 64;
                aReg[it] = make_float4(0.f, 0.f, 0.f, 0.f);
                if (r < rows) aReg[it] = *(const float4*)(A + (size_t)r * DIMV + kk + 16 + aCol);
                bReg[it] = *(const float4*)(W + (size_t)(kk + 16 + bRow + it * 8) * DIMV + colBase + bCol);
            }
        }
#pragma unroll
        for (int k = 0; k < 16; k++) {
            u64t rbp[4];
#pragma unroll
            for (int j = 0; j < 4; j++)
                rbp[j] = *(const u64t*)&Bs[k][tcol * 8 + 2 * j];
#pragma unroll
            for (int i = 0; i < 8; i++) {
                float a = As[k][trow * 8 + i];
                u64t ap; PACK_DUP(ap, a);
#pragma unroll
                for (int j = 0; j < 4; j++) FMA_X2(acc[i][j], ap, rbp[j], acc[i][j]);
            }
        }
        __syncthreads();
    }

#pragma unroll
    for (int i = 0; i < 8; i++) {
        int r = rowBase + trow * 8 + i;
        if (r >= rows) break;
#pragma unroll
        for (int j = 0; j < 4; j++) {
            int c = colBase + tcol * 8 + 2 * j;
            float v0, v1;
            UNPACK_X2(v0, v1, acc[i][j]);
            float2 o = make_float2(v0 + bias[c], v1 + bias[c + 1]);
            *(float2*)(outp + (size_t)r * DIMV + c) = o;
        }
    }
}

// ---------------------------------------------------------------------------
// Batched NT GEMM for dots:  C[r,c] = scale * A[r,:64] . B[c,:64], masked.
// ---------------------------------------------------------------------------
__global__ void __launch_bounds__(256, 2) dots_gemm(
    const float* __restrict__ Aall, const float* __restrict__ Ball,
    const int* __restrict__ mask, float* __restrict__ outAll,
    int rowsC, int colsC, int mrs, int mcs)
{
    int bh = blockIdx.z;
    const float* A = Aall + (size_t)bh * rowsC * DD;
    const float* Bm = Ball + (size_t)bh * colsC * DD;
    const int* mk = mask + (size_t)bh * NSEQ * MSEQ;
    float* outp = outAll + (size_t)bh * rowsC * colsC;

    __shared__ float As[16][132];
    __shared__ float Bs[16][132];
    int tid = threadIdx.x;
    int rowBase = blockIdx.y * 128;
    int colBase = blockIdx.x * 128;
    int trow = tid >> 4, tcol = tid & 15;
    u64t acc[8][4];
#pragma unroll
    for (int i = 0; i < 8; i++)
#pragma unroll
        for (int j = 0; j < 4; j++) acc[i][j] = 0ull;

    int aRow = tid >> 2, aCol = (tid & 3) << 2;

    float4 aReg[2], bReg[2];
#pragma unroll
    for (int it = 0; it < 2; ++it) {
        aReg[it] = *(const float4*)(A + (size_t)(rowBase + aRow + it * 64) * DD + aCol);
        bReg[it] = *(const float4*)(Bm + (size_t)(colBase + aRow + it * 64) * DD + aCol);
    }

    for (int kk = 0; kk < DD; kk += 16) {
#pragma unroll
        for (int it = 0; it < 2; ++it) {
            As[aCol + 0][aRow + it * 64] = aReg[it].x;
            As[aCol + 1][aRow + it * 64] = aReg[it].y;
            As[aCol + 2][aRow + it * 64] = aReg[it].z;
            As[aCol + 3][aRow + it * 64] = aReg[it].w;
            Bs[aCol + 0][aRow + it * 64] = bReg[it].x;
            Bs[aCol + 1][aRow + it * 64] = bReg[it].y;
            Bs[aCol + 2][aRow + it * 64] = bReg[it].z;
            Bs[aCol + 3][aRow + it * 64] = bReg[it].w;
        }
        __syncthreads();
        if (kk + 16 < DD) {
#pragma unroll
            for (int it = 0; it < 2; ++it) {
                aReg[it] = *(const float4*)(A + (size_t)(rowBase + aRow + it * 64) * DD + kk + 16 + aCol);
                bReg[it] = *(const float4*)(Bm + (size_t)(colBase + aRow + it * 64) * DD + kk + 16 + aCol);
            }
        }
#pragma unroll
        for (int k = 0; k < 16; k++) {
            u64t rbp[4];
#pragma unroll
            for (int j = 0; j < 4; j++)
                rbp[j] = *(const u64t*)&Bs[k][tcol * 8 + 2 * j];
#pragma unroll
            for (int i = 0; i < 8; i++) {
                float a = As[k][trow * 8 + i];
                u64t ap; PACK_DUP(ap, a);
#pragma unroll
                for (int j = 0; j < 4; j++) FMA_X2(acc[i][j], ap, rbp[j], acc[i][j]);
            }
        }
        __syncthreads();
    }

#pragma unroll
    for (int i = 0; i < 8; i++) {
        int r = rowBase + trow * 8 + i;
#pragma unroll
        for (int j = 0; j < 4; j++) {
            int c = colBase + tcol * 8 + 2 * j;
            float v0, v1;
            UNPACK_X2(v0, v1, acc[i][j]);
            v0 *= SCALEF; v1 *= SCALEF;
            if (mk[r * mrs + c * mcs]) v0 = NEGF;
            if (mk[r * mrs + (c + 1) * mcs]) v1 = NEGF;
            *(float2*)(outp + (size_t)r * colsC + c) = make_float2(v0, v1);
        }
    }
}

// ---------------------------------------------------------------------------
// Batched AV GEMM: C[rowsC,64] = A[rowsC,K] @ V[K,64]; write merged [b,s,h*64+d]
// ---------------------------------------------------------------------------
__global__ void __launch_bounds__(256, 2) av_gemm(
    const float* __restrict__ Aall, const float* __restrict__ Vall,
    float* __restrict__ outp, int rowsC, int Kdim, int seq)
{
    int bh = blockIdx.y;
    int b = bh / HH, h = bh % HH;
    const float* A = Aall + (size_t)bh * rowsC * Kdim;
    const float* V = Vall + (size_t)bh * Kdim * DD;

    __shared__ float As[16][132];
    __shared__ float Bs[16][68];
    int tid = threadIdx.x;
    int rowBase = blockIdx.x * 128;
    int trow = tid >> 4, tcol = tid & 15;
    u64t acc[8][2];
#pragma unroll
    for (int i = 0; i < 8; i++)
#pragma unroll
        for (int j = 0; j < 2; j++) acc[i][j] = 0ull;

    int aRow = tid >> 2, aCol = (tid & 3) << 2;
    int vRow = tid >> 4, vCol = (tid & 15) << 2;

    float4 aReg[2], vReg;
#pragma unroll
    for (int it = 0; it < 2; ++it)
        aReg[it] = *(const float4*)(A + (size_t)(rowBase + aRow + it * 64) * Kdim + aCol);
    vReg = *(const float4*)(V + (size_t)vRow * DD + vCol);

    for (int kk = 0; kk < Kdim; kk += 16) {
#pragma unroll
        for (int it = 0; it < 2; ++it) {
            As[aCol + 0][aRow + it * 64] = aReg[it].x;
            As[aCol + 1][aRow + it * 64] = aReg[it].y;
            As[aCol + 2][aRow + it * 64] = aReg[it].z;
            As[aCol + 3][aRow + it * 64] = aReg[it].w;
        }
        *(float4*)&Bs[vRow][vCol] = vReg;
        __syncthreads();
        if (kk + 16 < Kdim) {
#pragma unroll
            for (int it = 0; it < 2; ++it)
                aReg[it] = *(const float4*)(A + (size_t)(rowBase + aRow + it * 64) * Kdim + kk + 16 + aCol);
            vReg = *(const float4*)(V + (size_t)(kk + 16 + vRow) * DD + vCol);
        }
#pragma unroll
        for (int k = 0; k < 16; k++) {
            u64t rbp[2];
#pragma unroll
            for (int j = 0; j < 2; j++)
                rbp[j] = *(const u64t*)&Bs[k][tcol * 4 + 2 * j];
#pragma unroll
            for (int i = 0; i < 8; i++) {
                float a = As[k][trow * 8 + i];
                u64t ap; PACK_DUP(ap, a);
#pragma unroll
                for (int j = 0; j < 2; j++) FMA_X2(acc[i][j], ap, rbp[j], acc[i][j]);
            }
        }
        __syncthreads();
    }

#pragma unroll
    for (int i = 0; i < 8; i++) {
        int r = rowBase + trow * 8 + i;
#pragma unroll
        for (int j = 0; j < 2; j++) {
            int d = tcol * 4 + 2 * j;
            float v0, v1;
            UNPACK_X2(v0, v1, acc[i][j]);
            *(float2*)(outp + (size_t)(b * seq + r) * DIMV + h * 64 + d) = make_float2(v0, v1);
        }
    }
}

// ---------------------------------------------------------------------------
// Softmax stats, branch 1: per row (length 512): max, sum exp, sum exp(24*)
// ---------------------------------------------------------------------------
__global__ void __launch_bounds__(256) stats1_kernel()
{
    int gw = (blockIdx.x * 256 + threadIdx.x) >> 5;
    int lane = threadIdx.x & 31;
    const float* row = g_dots1 + (size_t)gw * MSEQ;
    float v[16], m = -3.4e38f;
#pragma unroll
    for (int i = 0; i < 16; i++) { v[i] = row[lane + 32 * i]; m = fmaxf(m, v[i]); }
#pragma unroll
    for (int o = 16; o > 0; o >>= 1) m = fmaxf(m, __shfl_xor_sync(0xffffffffu, m, o));
    float s = 0.f, sh = 0.f;
#pragma unroll
    for (int i = 0; i < 16; i++) {
        float t = v[i] - m;
        s += __expf(t);
        sh += __expf(TEMPF * t);
    }
#pragma unroll
    for (int o = 16; o > 0; o >>= 1) {
        s  += __shfl_xor_sync(0xffffffffu, s, o);
        sh += __shfl_xor_sync(0xffffffffu, sh, o);
    }
    if (lane == 0) { g_mx1[gw] = m; g_s1[gw] = s; g_sh1[gw] = sh; }
}

// ---------------------------------------------------------------------------
// Branch-1 apply: 32x32 tile transpose.
//   attn[n,m]   = exp(d-mx)/s1 * krd[m,n]      -> overwrite g_dots1 (n-major)
//   hot [m,n]   = exp(24(d-mx))/sh * krd[m,n]  -> out4 [b,h,m,n]
// ---------------------------------------------------------------------------
__global__ void apply1_kernel(const float* __restrict__ krd, float* __restrict__ out4)
{
    __shared__ float sd[32][33];
    __shared__ float sk[32][33];
    __shared__ float smx[32], ss1[32], ssh[32];
    int bh = blockIdx.z;
    int n0 = blockIdx.x * 32, m0 = blockIdx.y * 32;
    int tx = threadIdx.x, ty = threadIdx.y;
    const float* dbase = g_dots1 + (size_t)bh * NSEQ * MSEQ;
    const float* kbase = krd + (size_t)bh * MSEQ * NSEQ;

    int t = ty * 32 + tx;
    if (t < 32) {
        smx[t] = g_mx1[bh * NSEQ + n0 + t];
        ss1[t] = g_s1 [bh * NSEQ + n0 + t];
        ssh[t] = g_sh1[bh * NSEQ + n0 + t];
    }
#pragma unroll
    for (int it = 0; it < 4; it++) {
        int l = ty + 8 * it;
        sd[l][tx] = dbase[(size_t)(n0 + l) * MSEQ + m0 + tx];
        sk[l][tx] = kbase[(size_t)(m0 + l) * NSEQ + n0 + tx];
    }
    __syncthreads();

#pragma unroll
    for (int it = 0; it < 4; it++) {
        int nl = ty + 8 * it;
        float e = __expf(sd[nl][tx] - smx[nl]);
        float a = e / ss1[nl] * sk[tx][nl];
        g_dots1[(size_t)bh * NSEQ * MSEQ + (size_t)(n0 + nl) * MSEQ + m0 + tx] = a;
    }
#pragma unroll
    for (int it = 0; it < 4; it++) {
        int ml = ty + 8 * it;
        float e = __expf(TEMPF * (sd[tx][ml] - smx[tx]));
        float hv = e / ssh[tx] * sk[ml][tx];
        out4[(size_t)bh * MSEQ * NSEQ + (size_t)(m0 + ml) * NSEQ + n0 + tx] = hv;
    }
}

// ---------------------------------------------------------------------------
// Branch-2 fused softmax + krd apply: one block per row (length 2048)
// Reads dots2 ONCE, writes k_attn in place.
// ---------------------------------------------------------------------------
__global__ void __launch_bounds__(256) softmax2_kernel(const float* __restrict__ krd)
{
    __shared__ float red[8];
    int row = blockIdx.x;
    int tid = threadIdx.x;
    int lane = tid & 31, warp = tid >> 5;
    float* drow = g_dots2 + (size_t)row * NSEQ;
    const float* krow = krd + (size_t)row * NSEQ;

    float4 v0 = ((const float4*)drow)[tid];
    float4 v1 = ((const float4*)drow)[tid + 256];
    float m = fmaxf(fmaxf(fmaxf(v0.x, v0.y), fmaxf(v0.z, v0.w)),
                    fmaxf(fmaxf(v1.x, v1.y), fmaxf(v1.z, v1.w)));
#pragma unroll
    for (int o = 16; o > 0; o >>= 1) m = fmaxf(m, __shfl_xor_sync(0xffffffffu, m, o));
    if (lane == 0) red[warp] = m;
    __syncthreads();
    m = red[lane & 7];
#pragma unroll
    for (int o = 4; o > 0; o >>= 1) m = fmaxf(m, __shfl_xor_sync(0xffffffffu, m, o));

    float e0x = __expf(v0.x - m), e0y = __expf(v0.y - m), e0z = __expf(v0.z - m), e0w = __expf(v0.w - m);
    float e1x = __expf(v1.x - m), e1y = __expf(v1.y - m), e1z = __expf(v1.z - m), e1w = __expf(v1.w - m);
    float s = e0x + e0y + e0z + e0w + e1x + e1y + e1z + e1w;
#pragma unroll
    for (int o = 16; o > 0; o >>= 1) s += __shfl_xor_sync(0xffffffffu, s, o);
    __syncthreads();
    if (lane == 0) red[warp] = s;
    __syncthreads();
    s = red[lane & 7];
#pragma unroll
    for (int o = 4; o > 0; o >>= 1) s += __shfl_xor_sync(0xffffffffu, s, o);
    float inv = 1.f / s;

    float4 k0 = ((const float4*)krow)[tid];
    float4 k1 = ((const float4*)krow)[tid + 256];
    float4 o0 = make_float4(e0x * inv * k0.x, e0y * inv * k0.y, e0z * inv * k0.z, e0w * inv * k0.w);
    float4 o1 = make_float4(e1x * inv * k1.x, e1y * inv * k1.y, e1z * inv * k1.z, e1w * inv * k1.w);
    ((float4*)drow)[tid] = o0;
    ((float4*)drow)[tid + 256] = o1;
}

// ---------------------------------------------------------------------------
// Branch 3: cluster query vs kernel keys. One block per (b,h).
// ---------------------------------------------------------------------------
__global__ void __launch_bounds__(256) cluster_kernel(const int* __restrict__ mask)
{
    int bh = blockIdx.x;
    int b = bh / HH, h = bh % HH;
    __shared__ float q[64];
    __shared__ float p[512];
    __shared__ float red[256];
    int tid = threadIdx.x;
    const float* cq = g_cq + bh * 64;
    const float* kk = g_kk + (size_t)bh * MSEQ * DD;
    const float* kv = g_kv + (size_t)bh * MSEQ * DD;

    if (tid < 64) q[tid] = cq[tid];
    __syncthreads();

    for (int m = tid; m < MSEQ; m += 256) {
        float acc = 0.f;
#pragma unroll
        for (int d = 0; d < 64; d++) acc += q[d] * kk[m * 64 + d];
        acc *= SCALEF;
        if (mask[(size_t)bh * NSEQ * MSEQ + m]) acc = NEGF;
        p[m] = acc;
    }
    __syncthreads();

    red[tid] = fmaxf(p[tid], p[tid + 256]);
    __syncthreads();
    for (int s = 128; s > 0; s >>= 1) {
        if (tid < s) red[tid] = fmaxf(red[tid], red[tid + s]);
        __syncthreads();
    }
    float mx = red[0];
    __syncthreads();

    float e0 = __expf(p[tid] - mx), e1 = __expf(p[tid + 256] - mx);
    p[tid] = e0; p[tid + 256] = e1;
    red[tid] = e0 + e1;
    __syncthreads();
    for (int s = 128; s > 0; s >>= 1) {
        if (tid < s) red[tid] += red[tid + s];
        __syncthreads();
    }
    float inv = 1.f / red[0];
    __syncthreads();

    int d = tid & 63, part = tid >> 6;
    float acc = 0.f;
    for (int m = part * 128; m < part * 128 + 128; m++) acc += p[m] * kv[m * 64 + d];
    red[tid] = acc * inv;
    __syncthreads();
    if (part == 0)
        g_cO[b * DIMV + h * 64 + d] = red[d] + red[64 + d] + red[128 + d] + red[192 + d];
}

// ---------------------------------------------------------------------------
// Host launcher
// ---------------------------------------------------------------------------
extern "C" void kernel_launch(void* const* d_in, const int* in_sizes, int n_in,
                              void* d_out, int out_size)
{
    const float* x    = (const float*)d_in[0];
    const float* kx   = (const float*)d_in[1];
    const float* krd  = (const float*)d_in[2];
    const float* clst = (const float*)d_in[3];
    const int*   mask = (const int*)d_in[4];
    const float* Wqkv = (const float*)d_in[5];
    const float* Wout = (const float*)d_in[6];
    const float* bout = (const float*)d_in[7];
    float* out  = (float*)d_out;
    float* out1 = out + OUT1_OFF;
    float* out2 = out + OUT2_OFF;
    float* out3 = out + OUT3_OFF;
    float* out4 = out + OUT4_OFF;

    float *p_tq, *p_tk, *p_tv, *p_kq, *p_kk, *p_kv, *p_cq, *p_ck, *p_cv;
    float *p_d1, *p_d2, *p_attO, *p_kO, *p_cO;
    cudaGetSymbolAddress((void**)&p_tq, g_tq);
    cudaGetSymbolAddress((void**)&p_tk, g_tk);
    cudaGetSymbolAddress((void**)&p_tv, g_tv);
    cudaGetSymbolAddress((void**)&p_kq, g_kq);
    cudaGetSymbolAddress((void**)&p_kk, g_kk);
    cudaGetSymbolAddress((void**)&p_kv, g_kv);
    cudaGetSymbolAddress((void**)&p_cq, g_cq);
    cudaGetSymbolAddress((void**)&p_ck, g_ck);
    cudaGetSymbolAddress((void**)&p_cv, g_cv);
    cudaGetSymbolAddress((void**)&p_d1, g_dots1);
    cudaGetSymbolAddress((void**)&p_d2, g_dots2);
    cudaGetSymbolAddress((void**)&p_attO, g_attO);
    cudaGetSymbolAddress((void**)&p_kO, g_kO);
    cudaGetSymbolAddress((void**)&p_cO, g_cO);

    // 1) QKV projections
    qkv_gemm<<<dim3(TRIPLE / 128, (BB * NSEQ) / 128), 256>>>(x, Wqkv, p_tq, p_tk, p_tv, BB * NSEQ, NSEQ);
    qkv_gemm<<<dim3(TRIPLE / 128, (BB * MSEQ) / 128), 256>>>(kx, Wqkv, p_kq, p_kk, p_kv, BB * MSEQ, MSEQ);
    qkv_gemm<<<dim3(TRIPLE / 128, 1), 256>>>(clst, Wqkv, p_cq, p_ck, p_cv, BB, 1);

    // 2) dots (masked + scaled)
    dots_gemm<<<dim3(MSEQ / 128, NSEQ / 128, BH), 256>>>(p_tq, p_kk, mask, p_d1,
                                                         NSEQ, MSEQ, MSEQ, 1);
    dots_gemm<<<dim3(NSEQ / 128, MSEQ / 128, BH), 256>>>(p_kq, p_tk, mask, p_d2,
                                                         MSEQ, NSEQ, 1, MSEQ);

    // 3) softmax stats (branch 1) + fused softmax (branch 2)
    stats1_kernel<<<(BH * NSEQ) / 8, 256>>>();
    softmax2_kernel<<<BH * MSEQ, 256>>>(krd);

    // 4) branch-1 apply (attn / attn_hot)
    apply1_kernel<<<dim3(NSEQ / 32, MSEQ / 32, BH), dim3(32, 8)>>>(krd, out4);

    // 5) attention-value GEMMs
    av_gemm<<<dim3(NSEQ / 128, BH), 256>>>(p_d1, p_kv, p_attO, NSEQ, MSEQ, NSEQ);
    av_gemm<<<dim3(MSEQ / 128, BH), 256>>>(p_d2, p_tv, p_kO, MSEQ, NSEQ, MSEQ);

    // 6) cluster branch
    cluster_kernel<<<BH, 256>>>(mask);

    // 7) output projections
    proj_gemm<<<dim3(DIMV / 128, (BB * NSEQ) / 128), 256>>>(p_attO, Wout, bout, out1, BB * NSEQ);
    proj_gemm<<<dim3(DIMV / 128, (BB * MSEQ) / 128), 256>>>(p_kO, Wout, bout, out2, BB * MSEQ);
    proj_gemm<<<dim3(DIMV / 128, 1), 256>>>(p_cO, Wout, bout, out3, BB);
}

// round 10
// speedup vs baseline: 1.5409x; 1.5409x over previous
#include <cuda_runtime.h>

// ---------------------------------------------------------------------------
// Problem constants
// ---------------------------------------------------------------------------
#define BB    4
#define NSEQ  2048
#define MSEQ  512
#define HH    12
#define DD    64
#define DIMV  768
#define TRIPLE 2304
#define BH    (BB*HH)          // 48
#define SCALEF 0.125f
#define TEMPF  24.0f
#define NEGF  (-1e9f)

// Output segment offsets (floats)
#define OUT1_OFF 0
#define OUT2_OFF (BB*NSEQ*DIMV)                 // 6291456
#define OUT3_OFF (OUT2_OFF + BB*MSEQ*DIMV)      // 7864320
#define OUT4_OFF (OUT3_OFF + BB*DIMV)           // 7867392

// ---------------------------------------------------------------------------
// Packed f32x2 helpers (FFMA2 — only reachable via PTX)
// ---------------------------------------------------------------------------
#define FMA_X2(d, a, b, c) \
    asm("fma.rn.f32x2 %0, %1, %2, %3;" : "=l"(d) : "l"(a), "l"(b), "l"(c))
#define PACK_DUP(p, f) \
    asm("mov.b64 %0, {%1, %2};" : "=l"(p) : "f"(f), "f"(f))
#define UNPACK_X2(lo, hi, p) \
    asm("mov.b64 {%0, %1}, %2;" : "=f"(lo), "=f"(hi) : "l"(p))

typedef unsigned long long u64t;

// ---------------------------------------------------------------------------
// Device scratch (no cudaMalloc allowed)
// ---------------------------------------------------------------------------
__device__ float g_tq[BB*HH*NSEQ*DD];
__device__ float g_tk[BB*HH*NSEQ*DD];
__device__ float g_tv[BB*HH*NSEQ*DD];
__device__ float g_kq[BB*HH*MSEQ*DD];
__device__ float g_kk[BB*HH*MSEQ*DD];
__device__ float g_kv[BB*HH*MSEQ*DD];
__device__ float g_cq[BB*HH*DD];
__device__ float g_ck[BB*HH*DD];
__device__ float g_cv[BB*HH*DD];
__device__ float g_dots1[BB*HH*NSEQ*MSEQ];   // later overwritten with attn
__device__ float g_dots2[BB*HH*MSEQ*NSEQ];   // later overwritten with k_attn
__device__ float g_attO[BB*NSEQ*DIMV];
__device__ float g_kO[BB*MSEQ*DIMV];
__device__ float g_cO[BB*DIMV];
__device__ float g_mx1[BB*HH*NSEQ];
__device__ float g_s1 [BB*HH*NSEQ];
__device__ float g_sh1[BB*HH*NSEQ];

// ---------------------------------------------------------------------------
// QKV GEMM:  C[rows,2304] = A[rows,768] @ W[768,2304], scatter to q/k/v
// f32x2 inner loop, NO register prefetch (keeps regs <= 128 for 2 CTAs/SM)
// ---------------------------------------------------------------------------
__global__ void __launch_bounds__(256, 2) qkv_gemm(
    const float* __restrict__ A, const float* __restrict__ W,
    float* __restrict__ oq, float* __restrict__ ok2, float* __restrict__ ov,
    int rows, int seq)
{
    __shared__ float As[16][132];
    __shared__ float Bs[16][132];
    int tid = threadIdx.x;
    int rowBase = blockIdx.y * 128;
    int colBase = blockIdx.x * 128;
    int trow = tid >> 4, tcol = tid & 15;
    u64t acc[8][4];
#pragma unroll
    for (int i = 0; i < 8; i++)
#pragma unroll
        for (int j = 0; j < 4; j++) acc[i][j] = 0ull;

    int aRow = tid >> 2, aCol = (tid & 3) << 2;
    int bRow = tid >> 5, bCol = (tid & 31) << 2;

    for (int kk = 0; kk < DIMV; kk += 16) {
#pragma unroll
        for (int it = 0; it < 2; ++it) {
            int r = rowBase + aRow + it * 64;
            float4 v = make_float4(0.f, 0.f, 0.f, 0.f);
            if (r < rows) v = *(const float4*)(A + (size_t)r * DIMV + kk + aCol);
            As[aCol + 0][aRow + it * 64] = v.x;
            As[aCol + 1][aRow + it * 64] = v.y;
            As[aCol + 2][aRow + it * 64] = v.z;
            As[aCol + 3][aRow + it * 64] = v.w;
        }
#pragma unroll
        for (int it = 0; it < 2; ++it) {
            int kr = bRow + it * 8;
            float4 v = *(const float4*)(W + (size_t)(kk + kr) * TRIPLE + colBase + bCol);
            *(float4*)&Bs[kr][bCol] = v;
        }
        __syncthreads();
#pragma unroll
        for (int k = 0; k < 16; k++) {
            u64t rbp[4];
#pragma unroll
            for (int j = 0; j < 4; j++)
                rbp[j] = *(const u64t*)&Bs[k][tcol * 8 + 2 * j];
#pragma unroll
            for (int i = 0; i < 8; i++) {
                float a = As[k][trow * 8 + i];
                u64t ap; PACK_DUP(ap, a);
#pragma unroll
                for (int j = 0; j < 4; j++) FMA_X2(acc[i][j], ap, rbp[j], acc[i][j]);
            }
        }
        __syncthreads();
    }

#pragma unroll
    for (int i = 0; i < 8; i++) {
        int r = rowBase + trow * 8 + i;
        if (r >= rows) break;
        int b = r / seq, s = r % seq;
#pragma unroll
        for (int j = 0; j < 4; j++) {
            float v0, v1;
            UNPACK_X2(v0, v1, acc[i][j]);
#pragma unroll
            for (int u = 0; u < 2; u++) {
                int c = colBase + tcol * 8 + 2 * j + u;
                float v = u ? v1 : v0;
                int part = c / DIMV, cc = c % DIMV;
                int h = cc >> 6, d = cc & 63;
                int idx = ((b * HH + h) * seq + s) * DD + d;
                if (part == 0) oq[idx] = v;
                else if (part == 1) ok2[idx] = v;
                else ov[idx] = v;
            }
        }
    }
}

// ---------------------------------------------------------------------------
// Projection GEMM: out[rows,768] = A[rows,768] @ W[768,768] + bias
// ---------------------------------------------------------------------------
__global__ void __launch_bounds__(256, 2) proj_gemm(
    const float* __restrict__ A, const float* __restrict__ W,
    const float* __restrict__ bias, float* __restrict__ outp, int rows)
{
    __shared__ float As[16][132];
    __shared__ float Bs[16][132];
    int tid = threadIdx.x;
    int rowBase = blockIdx.y * 128;
    int colBase = blockIdx.x * 128;
    int trow = tid >> 4, tcol = tid & 15;
    u64t acc[8][4];
#pragma unroll
    for (int i = 0; i < 8; i++)
#pragma unroll
        for (int j = 0; j < 4; j++) acc[i][j] = 0ull;

    int aRow = tid >> 2, aCol = (tid & 3) << 2;
    int bRow = tid >> 5, bCol = (tid & 31) << 2;

    for (int kk = 0; kk < DIMV; kk += 16) {
#pragma unroll
        for (int it = 0; it < 2; ++it) {
            int r = rowBase + aRow + it * 64;
            float4 v = make_float4(0.f, 0.f, 0.f, 0.f);
            if (r < rows) v = *(const float4*)(A + (size_t)r * DIMV + kk + aCol);
            As[aCol + 0][aRow + it * 64] = v.x;
            As[aCol + 1][aRow + it * 64] = v.y;
            As[aCol + 2][aRow + it * 64] = v.z;
            As[aCol + 3][aRow + it * 64] = v.w;
        }
#pragma unroll
        for (int it = 0; it < 2; ++it) {
            int kr = bRow + it * 8;
            float4 v = *(const float4*)(W + (size_t)(kk + kr) * DIMV + colBase + bCol);
            *(float4*)&Bs[kr][bCol] = v;
        }
        __syncthreads();
#pragma unroll
        for (int k = 0; k < 16; k++) {
            u64t rbp[4];
#pragma unroll
            for (int j = 0; j < 4; j++)
                rbp[j] = *(const u64t*)&Bs[k][tcol * 8 + 2 * j];
#pragma unroll
            for (int i = 0; i < 8; i++) {
                float a = As[k][trow * 8 + i];
                u64t ap; PACK_DUP(ap, a);
#pragma unroll
                for (int j = 0; j < 4; j++) FMA_X2(acc[i][j], ap, rbp[j], acc[i][j]);
            }
        }
        __syncthreads();
    }

#pragma unroll
    for (int i = 0; i < 8; i++) {
        int r = rowBase + trow * 8 + i;
        if (r >= rows) break;
#pragma unroll
        for (int j = 0; j < 4; j++) {
            int c = colBase + tcol * 8 + 2 * j;
            float v0, v1;
            UNPACK_X2(v0, v1, acc[i][j]);
            float2 o = make_float2(v0 + bias[c], v1 + bias[c + 1]);
            *(float2*)(outp + (size_t)r * DIMV + c) = o;
        }
    }
}

// ---------------------------------------------------------------------------
// Batched NT GEMM for dots:  C[r,c] = scale * A[r,:64] . B[c,:64], masked.
// ---------------------------------------------------------------------------
__global__ void __launch_bounds__(256, 2) dots_gemm(
    const float* __restrict__ Aall, const float* __restrict__ Ball,
    const int* __restrict__ mask, float* __restrict__ outAll,
    int rowsC, int colsC, int mrs, int mcs)
{
    int bh = blockIdx.z;
    const float* A = Aall + (size_t)bh * rowsC * DD;
    const float* Bm = Ball + (size_t)bh * colsC * DD;
    const int* mk = mask + (size_t)bh * NSEQ * MSEQ;
    float* outp = outAll + (size_t)bh * rowsC * colsC;

    __shared__ float As[16][132];
    __shared__ float Bs[16][132];
    int tid = threadIdx.x;
    int rowBase = blockIdx.y * 128;
    int colBase = blockIdx.x * 128;
    int trow = tid >> 4, tcol = tid & 15;
    u64t acc[8][4];
#pragma unroll
    for (int i = 0; i < 8; i++)
#pragma unroll
        for (int j = 0; j < 4; j++) acc[i][j] = 0ull;

    int aRow = tid >> 2, aCol = (tid & 3) << 2;

    for (int kk = 0; kk < DD; kk += 16) {
#pragma unroll
        for (int it = 0; it < 2; ++it) {
            float4 v = *(const float4*)(A + (size_t)(rowBase + aRow + it * 64) * DD + kk + aCol);
            As[aCol + 0][aRow + it * 64] = v.x;
            As[aCol + 1][aRow + it * 64] = v.y;
            As[aCol + 2][aRow + it * 64] = v.z;
            As[aCol + 3][aRow + it * 64] = v.w;
            float4 w = *(const float4*)(Bm + (size_t)(colBase + aRow + it * 64) * DD + kk + aCol);
            Bs[aCol + 0][aRow + it * 64] = w.x;
            Bs[aCol + 1][aRow + it * 64] = w.y;
            Bs[aCol + 2][aRow + it * 64] = w.z;
            Bs[aCol + 3][aRow + it * 64] = w.w;
        }
        __syncthreads();
#pragma unroll
        for (int k = 0; k < 16; k++) {
            u64t rbp[4];
#pragma unroll
            for (int j = 0; j < 4; j++)
                rbp[j] = *(const u64t*)&Bs[k][tcol * 8 + 2 * j];
#pragma unroll
            for (int i = 0; i < 8; i++) {
                float a = As[k][trow * 8 + i];
                u64t ap; PACK_DUP(ap, a);
#pragma unroll
                for (int j = 0; j < 4; j++) FMA_X2(acc[i][j], ap, rbp[j], acc[i][j]);
            }
        }
        __syncthreads();
    }

#pragma unroll
    for (int i = 0; i < 8; i++) {
        int r = rowBase + trow * 8 + i;
#pragma unroll
        for (int j = 0; j < 4; j++) {
            int c = colBase + tcol * 8 + 2 * j;
            float v0, v1;
            UNPACK_X2(v0, v1, acc[i][j]);
            v0 *= SCALEF; v1 *= SCALEF;
            if (mk[r * mrs + c * mcs]) v0 = NEGF;
            if (mk[r * mrs + (c + 1) * mcs]) v1 = NEGF;
            *(float2*)(outp + (size_t)r * colsC + c) = make_float2(v0, v1);
        }
    }
}

// ---------------------------------------------------------------------------
// Batched AV GEMM: C[rowsC,64] = A[rowsC,K] @ V[K,64]; write merged [b,s,h*64+d]
// ---------------------------------------------------------------------------
__global__ void __launch_bounds__(256, 2) av_gemm(
    const float* __restrict__ Aall, const float* __restrict__ Vall,
    float* __restrict__ outp, int rowsC, int Kdim, int seq)
{
    int bh = blockIdx.y;
    int b = bh / HH, h = bh % HH;
    const float* A = Aall + (size_t)bh * rowsC * Kdim;
    const float* V = Vall + (size_t)bh * Kdim * DD;

    __shared__ float As[16][132];
    __shared__ float Bs[16][68];
    int tid = threadIdx.x;
    int rowBase = blockIdx.x * 128;
    int trow = tid >> 4, tcol = tid & 15;
    u64t acc[8][2];
#pragma unroll
    for (int i = 0; i < 8; i++)
#pragma unroll
        for (int j = 0; j < 2; j++) acc[i][j] = 0ull;

    int aRow = tid >> 2, aCol = (tid & 3) << 2;
    int vRow = tid >> 4, vCol = (tid & 15) << 2;

    for (int kk = 0; kk < Kdim; kk += 16) {
#pragma unroll
        for (int it = 0; it < 2; ++it) {
            float4 v = *(const float4*)(A + (size_t)(rowBase + aRow + it * 64) * Kdim + kk + aCol);
            As[aCol + 0][aRow + it * 64] = v.x;
            As[aCol + 1][aRow + it * 64] = v.y;
            As[aCol + 2][aRow + it * 64] = v.z;
            As[aCol + 3][aRow + it * 64] = v.w;
        }
        {
            float4 v = *(const float4*)(V + (size_t)(kk + vRow) * DD + vCol);
            *(float4*)&Bs[vRow][vCol] = v;
        }
        __syncthreads();
#pragma unroll
        for (int k = 0; k < 16; k++) {
            u64t rbp[2];
#pragma unroll
            for (int j = 0; j < 2; j++)
                rbp[j] = *(const u64t*)&Bs[k][tcol * 4 + 2 * j];
#pragma unroll
            for (int i = 0; i < 8; i++) {
                float a = As[k][trow * 8 + i];
                u64t ap; PACK_DUP(ap, a);
#pragma unroll
                for (int j = 0; j < 2; j++) FMA_X2(acc[i][j], ap, rbp[j], acc[i][j]);
            }
        }
        __syncthreads();
    }

#pragma unroll
    for (int i = 0; i < 8; i++) {
        int r = rowBase + trow * 8 + i;
#pragma unroll
        for (int j = 0; j < 2; j++) {
            int d = tcol * 4 + 2 * j;
            float v0, v1;
            UNPACK_X2(v0, v1, acc[i][j]);
            *(float2*)(outp + (size_t)(b * seq + r) * DIMV + h * 64 + d) = make_float2(v0, v1);
        }
    }
}

// ---------------------------------------------------------------------------
// Softmax stats, branch 1: per row (length 512): max, sum exp, sum exp(24*)
// ---------------------------------------------------------------------------
__global__ void __launch_bounds__(256) stats1_kernel()
{
    int gw = (blockIdx.x * 256 + threadIdx.x) >> 5;
    int lane = threadIdx.x & 31;
    const float* row = g_dots1 + (size_t)gw * MSEQ;
    float v[16], m = -3.4e38f;
#pragma unroll
    for (int i = 0; i < 16; i++) { v[i] = row[lane + 32 * i]; m = fmaxf(m, v[i]); }
#pragma unroll
    for (int o = 16; o > 0; o >>= 1) m = fmaxf(m, __shfl_xor_sync(0xffffffffu, m, o));
    float s = 0.f, sh = 0.f;
#pragma unroll
    for (int i = 0; i < 16; i++) {
        float t = v[i] - m;
        s += __expf(t);
        sh += __expf(TEMPF * t);
    }
#pragma unroll
    for (int o = 16; o > 0; o >>= 1) {
        s  += __shfl_xor_sync(0xffffffffu, s, o);
        sh += __shfl_xor_sync(0xffffffffu, sh, o);
    }
    if (lane == 0) { g_mx1[gw] = m; g_s1[gw] = s; g_sh1[gw] = sh; }
}

// ---------------------------------------------------------------------------
// Branch-1 apply: 32x32 tile transpose.
//   attn[n,m]   = exp(d-mx)/s1 * krd[m,n]      -> overwrite g_dots1 (n-major)
//   hot [m,n]   = exp(24(d-mx))/sh * krd[m,n]  -> out4 [b,h,m,n]
// ---------------------------------------------------------------------------
__global__ void apply1_kernel(const float* __restrict__ krd, float* __restrict__ out4)
{
    __shared__ float sd[32][33];
    __shared__ float sk[32][33];
    __shared__ float smx[32], ss1[32], ssh[32];
    int bh = blockIdx.z;
    int n0 = blockIdx.x * 32, m0 = blockIdx.y * 32;
    int tx = threadIdx.x, ty = threadIdx.y;
    const float* dbase = g_dots1 + (size_t)bh * NSEQ * MSEQ;
    const float* kbase = krd + (size_t)bh * MSEQ * NSEQ;

    int t = ty * 32 + tx;
    if (t < 32) {
        smx[t] = g_mx1[bh * NSEQ + n0 + t];
        ss1[t] = g_s1 [bh * NSEQ + n0 + t];
        ssh[t] = g_sh1[bh * NSEQ + n0 + t];
    }
#pragma unroll
    for (int it = 0; it < 4; it++) {
        int l = ty + 8 * it;
        sd[l][tx] = dbase[(size_t)(n0 + l) * MSEQ + m0 + tx];
        sk[l][tx] = kbase[(size_t)(m0 + l) * NSEQ + n0 + tx];
    }
    __syncthreads();

#pragma unroll
    for (int it = 0; it < 4; it++) {
        int nl = ty + 8 * it;
        float e = __expf(sd[nl][tx] - smx[nl]);
        float a = e / ss1[nl] * sk[tx][nl];
        g_dots1[(size_t)bh * NSEQ * MSEQ + (size_t)(n0 + nl) * MSEQ + m0 + tx] = a;
    }
#pragma unroll
    for (int it = 0; it < 4; it++) {
        int ml = ty + 8 * it;
        float e = __expf(TEMPF * (sd[tx][ml] - smx[tx]));
        float hv = e / ssh[tx] * sk[ml][tx];
        out4[(size_t)bh * MSEQ * NSEQ + (size_t)(m0 + ml) * NSEQ + n0 + tx] = hv;
    }
}

// ---------------------------------------------------------------------------
// Branch-2 fused softmax + krd apply: one block per row (length 2048)
// Reads dots2 ONCE, writes k_attn in place.
// ---------------------------------------------------------------------------
__global__ void __launch_bounds__(256) softmax2_kernel(const float* __restrict__ krd)
{
    __shared__ float red[8];
    int row = blockIdx.x;
    int tid = threadIdx.x;
    int lane = tid & 31, warp = tid >> 5;
    float* drow = g_dots2 + (size_t)row * NSEQ;
    const float* krow = krd + (size_t)row * NSEQ;

    float4 v0 = ((const float4*)drow)[tid];
    float4 v1 = ((const float4*)drow)[tid + 256];
    float m = fmaxf(fmaxf(fmaxf(v0.x, v0.y), fmaxf(v0.z, v0.w)),
                    fmaxf(fmaxf(v1.x, v1.y), fmaxf(v1.z, v1.w)));
#pragma unroll
    for (int o = 16; o > 0; o >>= 1) m = fmaxf(m, __shfl_xor_sync(0xffffffffu, m, o));
    if (lane == 0) red[warp] = m;
    __syncthreads();
    m = red[lane & 7];
#pragma unroll
    for (int o = 4; o > 0; o >>= 1) m = fmaxf(m, __shfl_xor_sync(0xffffffffu, m, o));

    float e0x = __expf(v0.x - m), e0y = __expf(v0.y - m), e0z = __expf(v0.z - m), e0w = __expf(v0.w - m);
    float e1x = __expf(v1.x - m), e1y = __expf(v1.y - m), e1z = __expf(v1.z - m), e1w = __expf(v1.w - m);
    float s = e0x + e0y + e0z + e0w + e1x + e1y + e1z + e1w;
#pragma unroll
    for (int o = 16; o > 0; o >>= 1) s += __shfl_xor_sync(0xffffffffu, s, o);
    __syncthreads();
    if (lane == 0) red[warp] = s;
    __syncthreads();
    s = red[lane & 7];
#pragma unroll
    for (int o = 4; o > 0; o >>= 1) s += __shfl_xor_sync(0xffffffffu, s, o);
    float inv = 1.f / s;

    float4 k0 = ((const float4*)krow)[tid];
    float4 k1 = ((const float4*)krow)[tid + 256];
    float4 o0 = make_float4(e0x * inv * k0.x, e0y * inv * k0.y, e0z * inv * k0.z, e0w * inv * k0.w);
    float4 o1 = make_float4(e1x * inv * k1.x, e1y * inv * k1.y, e1z * inv * k1.z, e1w * inv * k1.w);
    ((float4*)drow)[tid] = o0;
    ((float4*)drow)[tid + 256] = o1;
}

// ---------------------------------------------------------------------------
// Branch 3: cluster query vs kernel keys. One block per (b,h).
// ---------------------------------------------------------------------------
__global__ void __launch_bounds__(256) cluster_kernel(const int* __restrict__ mask)
{
    int bh = blockIdx.x;
    int b = bh / HH, h = bh % HH;
    __shared__ float q[64];
    __shared__ float p[512];
    __shared__ float red[256];
    int tid = threadIdx.x;
    const float* cq = g_cq + bh * 64;
    const float* kk = g_kk + (size_t)bh * MSEQ * DD;
    const float* kv = g_kv + (size_t)bh * MSEQ * DD;

    if (tid < 64) q[tid] = cq[tid];
    __syncthreads();

    for (int m = tid; m < MSEQ; m += 256) {
        float acc = 0.f;
#pragma unroll
        for (int d = 0; d < 64; d++) acc += q[d] * kk[m * 64 + d];
        acc *= SCALEF;
        if (mask[(size_t)bh * NSEQ * MSEQ + m]) acc = NEGF;
        p[m] = acc;
    }
    __syncthreads();

    red[tid] = fmaxf(p[tid], p[tid + 256]);
    __syncthreads();
    for (int s = 128; s > 0; s >>= 1) {
        if (tid < s) red[tid] = fmaxf(red[tid], red[tid + s]);
        __syncthreads();
    }
    float mx = red[0];
    __syncthreads();

    float e0 = __expf(p[tid] - mx), e1 = __expf(p[tid + 256] - mx);
    p[tid] = e0; p[tid + 256] = e1;
    red[tid] = e0 + e1;
    __syncthreads();
    for (int s = 128; s > 0; s >>= 1) {
        if (tid < s) red[tid] += red[tid + s];
        __syncthreads();
    }
    float inv = 1.f / red[0];
    __syncthreads();

    int d = tid & 63, part = tid >> 6;
    float acc = 0.f;
    for (int m = part * 128; m < part * 128 + 128; m++) acc += p[m] * kv[m * 64 + d];
    red[tid] = acc * inv;
    __syncthreads();
    if (part == 0)
        g_cO[b * DIMV + h * 64 + d] = red[d] + red[64 + d] + red[128 + d] + red[192 + d];
}

// ---------------------------------------------------------------------------
// Host launcher
// ---------------------------------------------------------------------------
extern "C" void kernel_launch(void* const* d_in, const int* in_sizes, int n_in,
                              void* d_out, int out_size)
{
    const float* x    = (const float*)d_in[0];
    const float* kx   = (const float*)d_in[1];
    const float* krd  = (const float*)d_in[2];
    const float* clst = (const float*)d_in[3];
    const int*   mask = (const int*)d_in[4];
    const float* Wqkv = (const float*)d_in[5];
    const float* Wout = (const float*)d_in[6];
    const float* bout = (const float*)d_in[7];
    float* out  = (float*)d_out;
    float* out1 = out + OUT1_OFF;
    float* out2 = out + OUT2_OFF;
    float* out3 = out + OUT3_OFF;
    float* out4 = out + OUT4_OFF;

    float *p_tq, *p_tk, *p_tv, *p_kq, *p_kk, *p_kv, *p_cq, *p_ck, *p_cv;
    float *p_d1, *p_d2, *p_attO, *p_kO, *p_cO;
    cudaGetSymbolAddress((void**)&p_tq, g_tq);
    cudaGetSymbolAddress((void**)&p_tk, g_tk);
    cudaGetSymbolAddress((void**)&p_tv, g_tv);
    cudaGetSymbolAddress((void**)&p_kq, g_kq);
    cudaGetSymbolAddress((void**)&p_kk, g_kk);
    cudaGetSymbolAddress((void**)&p_kv, g_kv);
    cudaGetSymbolAddress((void**)&p_cq, g_cq);
    cudaGetSymbolAddress((void**)&p_ck, g_ck);
    cudaGetSymbolAddress((void**)&p_cv, g_cv);
    cudaGetSymbolAddress((void**)&p_d1, g_dots1);
    cudaGetSymbolAddress((void**)&p_d2, g_dots2);
    cudaGetSymbolAddress((void**)&p_attO, g_attO);
    cudaGetSymbolAddress((void**)&p_kO, g_kO);
    cudaGetSymbolAddress((void**)&p_cO, g_cO);

    // 1) QKV projections
    qkv_gemm<<<dim3(TRIPLE / 128, (BB * NSEQ) / 128), 256>>>(x, Wqkv, p_tq, p_tk, p_tv, BB * NSEQ, NSEQ);
    qkv_gemm<<<dim3(TRIPLE / 128, (BB * MSEQ) / 128), 256>>>(kx, Wqkv, p_kq, p_kk, p_kv, BB * MSEQ, MSEQ);
    qkv_gemm<<<dim3(TRIPLE / 128, 1), 256>>>(clst, Wqkv, p_cq, p_ck, p_cv, BB, 1);

    // 2) dots (masked + scaled)
    dots_gemm<<<dim3(MSEQ / 128, NSEQ / 128, BH), 256>>>(p_tq, p_kk, mask, p_d1,
                                                         NSEQ, MSEQ, MSEQ, 1);
    dots_gemm<<<dim3(NSEQ / 128, MSEQ / 128, BH), 256>>>(p_kq, p_tk, mask, p_d2,
                                                         MSEQ, NSEQ, 1, MSEQ);

    // 3) softmax stats (branch 1) + fused softmax (branch 2)
    stats1_kernel<<<(BH * NSEQ) / 8, 256>>>();
    softmax2_kernel<<<BH * MSEQ, 256>>>(krd);

    // 4) branch-1 apply (attn / attn_hot)
    apply1_kernel<<<dim3(NSEQ / 32, MSEQ / 32, BH), dim3(32, 8)>>>(krd, out4);

    // 5) attention-value GEMMs
    av_gemm<<<dim3(NSEQ / 128, BH), 256>>>(p_d1, p_kv, p_attO, NSEQ, MSEQ, NSEQ);
    av_gemm<<<dim3(MSEQ / 128, BH), 256>>>(p_d2, p_tv, p_kO, MSEQ, NSEQ, MSEQ);

    // 6) cluster branch
    cluster_kernel<<<BH, 256>>>(mask);

    // 7) output projections
    proj_gemm<<<dim3(DIMV / 128, (BB * NSEQ) / 128), 256>>>(p_attO, Wout, bout, out1, BB * NSEQ);
    proj_gemm<<<dim3(DIMV / 128, (BB * MSEQ) / 128), 256>>>(p_kO, Wout, bout, out2, BB * MSEQ);
    proj_gemm<<<dim3(DIMV / 128, 1), 256>>>(p_cO, Wout, bout, out3, BB);
}

// round 11
// speedup vs baseline: 1.5478x; 1.0044x over previous
#include <cuda_runtime.h>

// ---------------------------------------------------------------------------
// Problem constants
// ---------------------------------------------------------------------------
#define BB    4
#define NSEQ  2048
#define MSEQ  512
#define HH    12
#define DD    64
#define DIMV  768
#define TRIPLE 2304
#define BH    (BB*HH)          // 48
#define SCALEF 0.125f
#define TEMPF  24.0f
#define NEGF  (-1e9f)

// Output segment offsets (floats)
#define OUT1_OFF 0
#define OUT2_OFF (BB*NSEQ*DIMV)                 // 6291456
#define OUT3_OFF (OUT2_OFF + BB*MSEQ*DIMV)      // 7864320
#define OUT4_OFF (OUT3_OFF + BB*DIMV)           // 7867392

// ---------------------------------------------------------------------------
// Packed f32x2 helpers (FFMA2 — only reachable via PTX)
// ---------------------------------------------------------------------------
#define FMA_X2(d, a, b, c) \
    asm("fma.rn.f32x2 %0, %1, %2, %3;" : "=l"(d) : "l"(a), "l"(b), "l"(c))
#define PACK_DUP(p, f) \
    asm("mov.b64 %0, {%1, %2};" : "=l"(p) : "f"(f), "f"(f))
#define UNPACK_X2(lo, hi, p) \
    asm("mov.b64 {%0, %1}, %2;" : "=f"(lo), "=f"(hi) : "l"(p))

typedef unsigned long long u64t;

// ---------------------------------------------------------------------------
// Device scratch (no cudaMalloc allowed)
// ---------------------------------------------------------------------------
__device__ float g_tq[BB*HH*NSEQ*DD];
__device__ float g_tk[BB*HH*NSEQ*DD];
__device__ float g_tv[BB*HH*NSEQ*DD];
__device__ float g_kq[BB*HH*MSEQ*DD];
__device__ float g_kk[BB*HH*MSEQ*DD];
__device__ float g_kv[BB*HH*MSEQ*DD];
__device__ float g_cq[BB*HH*DD];
__device__ float g_ck[BB*HH*DD];
__device__ float g_cv[BB*HH*DD];
__device__ float g_dots1[BB*HH*NSEQ*MSEQ];   // later overwritten with attn
__device__ float g_dots2[BB*HH*MSEQ*NSEQ];   // later overwritten with k_attn
__device__ float g_attO[BB*NSEQ*DIMV];
__device__ float g_kO[BB*MSEQ*DIMV];
__device__ float g_cO[BB*DIMV];
__device__ float g_mx1[BB*HH*NSEQ];
__device__ float g_s1 [BB*HH*NSEQ];
__device__ float g_sh1[BB*HH*NSEQ];

// Inner-loop body shared by the 128-wide GEMMs: A via 2x float4 (broadcast),
// B via 2x longlong2 (LDS.128 delivering FFMA2 operand pairs directly).
#define GEMM_INNER_16(As, Bs, acc)                                         \
    _Pragma("unroll")                                                      \
    for (int k = 0; k < 16; k++) {                                         \
        float4 ra0 = *(const float4*)&As[k][trow * 8];                     \
        float4 ra1 = *(const float4*)&As[k][trow * 8 + 4];                 \
        longlong2 rb0 = *(const longlong2*)&Bs[k][tcol * 8];               \
        longlong2 rb1 = *(const longlong2*)&Bs[k][tcol * 8 + 4];           \
        u64t rbp[4] = {(u64t)rb0.x, (u64t)rb0.y, (u64t)rb1.x, (u64t)rb1.y};\
        float a_s[8] = {ra0.x, ra0.y, ra0.z, ra0.w,                        \
                        ra1.x, ra1.y, ra1.z, ra1.w};                       \
        _Pragma("unroll")                                                  \
        for (int i = 0; i < 8; i++) {                                      \
            u64t ap; PACK_DUP(ap, a_s[i]);                                 \
            _Pragma("unroll")                                              \
            for (int j = 0; j < 4; j++) FMA_X2(acc[i][j], ap, rbp[j], acc[i][j]); \
        }                                                                  \
    }

// ---------------------------------------------------------------------------
// QKV GEMM:  C[rows,2304] = A[rows,768] @ W[768,2304], scatter to q/k/v
// ---------------------------------------------------------------------------
__global__ void __launch_bounds__(256, 2) qkv_gemm(
    const float* __restrict__ A, const float* __restrict__ W,
    float* __restrict__ oq, float* __restrict__ ok2, float* __restrict__ ov,
    int rows, int seq)
{
    __shared__ __align__(16) float As[16][132];
    __shared__ __align__(16) float Bs[16][132];
    int tid = threadIdx.x;
    int rowBase = blockIdx.y * 128;
    int colBase = blockIdx.x * 128;
    int trow = tid >> 4, tcol = tid & 15;
    u64t acc[8][4];
#pragma unroll
    for (int i = 0; i < 8; i++)
#pragma unroll
        for (int j = 0; j < 4; j++) acc[i][j] = 0ull;

    int aRow = tid >> 2, aCol = (tid & 3) << 2;
    int bRow = tid >> 5, bCol = (tid & 31) << 2;

    for (int kk = 0; kk < DIMV; kk += 16) {
#pragma unroll
        for (int it = 0; it < 2; ++it) {
            int r = rowBase + aRow + it * 64;
            float4 v = make_float4(0.f, 0.f, 0.f, 0.f);
            if (r < rows) v = *(const float4*)(A + (size_t)r * DIMV + kk + aCol);
            As[aCol + 0][aRow + it * 64] = v.x;
            As[aCol + 1][aRow + it * 64] = v.y;
            As[aCol + 2][aRow + it * 64] = v.z;
            As[aCol + 3][aRow + it * 64] = v.w;
        }
#pragma unroll
        for (int it = 0; it < 2; ++it) {
            int kr = bRow + it * 8;
            float4 v = *(const float4*)(W + (size_t)(kk + kr) * TRIPLE + colBase + bCol);
            *(float4*)&Bs[kr][bCol] = v;
        }
        __syncthreads();
        GEMM_INNER_16(As, Bs, acc)
        __syncthreads();
    }

#pragma unroll
    for (int i = 0; i < 8; i++) {
        int r = rowBase + trow * 8 + i;
        if (r >= rows) break;
        int b = r / seq, s = r % seq;
#pragma unroll
        for (int j = 0; j < 4; j++) {
            float v0, v1;
            UNPACK_X2(v0, v1, acc[i][j]);
#pragma unroll
            for (int u = 0; u < 2; u++) {
                int c = colBase + tcol * 8 + 2 * j + u;
                float v = u ? v1 : v0;
                int part = c / DIMV, cc = c % DIMV;
                int h = cc >> 6, d = cc & 63;
                int idx = ((b * HH + h) * seq + s) * DD + d;
                if (part == 0) oq[idx] = v;
                else if (part == 1) ok2[idx] = v;
                else ov[idx] = v;
            }
        }
    }
}

// ---------------------------------------------------------------------------
// Projection GEMM: out[rows,768] = A[rows,768] @ W[768,768] + bias
// ---------------------------------------------------------------------------
__global__ void __launch_bounds__(256, 2) proj_gemm(
    const float* __restrict__ A, const float* __restrict__ W,
    const float* __restrict__ bias, float* __restrict__ outp, int rows)
{
    __shared__ __align__(16) float As[16][132];
    __shared__ __align__(16) float Bs[16][132];
    int tid = threadIdx.x;
    int rowBase = blockIdx.y * 128;
    int colBase = blockIdx.x * 128;
    int trow = tid >> 4, tcol = tid & 15;
    u64t acc[8][4];
#pragma unroll
    for (int i = 0; i < 8; i++)
#pragma unroll
        for (int j = 0; j < 4; j++) acc[i][j] = 0ull;

    int aRow = tid >> 2, aCol = (tid & 3) << 2;
    int bRow = tid >> 5, bCol = (tid & 31) << 2;

    for (int kk = 0; kk < DIMV; kk += 16) {
#pragma unroll
        for (int it = 0; it < 2; ++it) {
            int r = rowBase + aRow + it * 64;
            float4 v = make_float4(0.f, 0.f, 0.f, 0.f);
            if (r < rows) v = *(const float4*)(A + (size_t)r * DIMV + kk + aCol);
            As[aCol + 0][aRow + it * 64] = v.x;
            As[aCol + 1][aRow + it * 64] = v.y;
            As[aCol + 2][aRow + it * 64] = v.z;
            As[aCol + 3][aRow + it * 64] = v.w;
        }
#pragma unroll
        for (int it = 0; it < 2; ++it) {
            int kr = bRow + it * 8;
            float4 v = *(const float4*)(W + (size_t)(kk + kr) * DIMV + colBase + bCol);
            *(float4*)&Bs[kr][bCol] = v;
        }
        __syncthreads();
        GEMM_INNER_16(As, Bs, acc)
        __syncthreads();
    }

#pragma unroll
    for (int i = 0; i < 8; i++) {
        int r = rowBase + trow * 8 + i;
        if (r >= rows) break;
#pragma unroll
        for (int j = 0; j < 4; j++) {
            int c = colBase + tcol * 8 + 2 * j;
            float v0, v1;
            UNPACK_X2(v0, v1, acc[i][j]);
            float2 o = make_float2(v0 + bias[c], v1 + bias[c + 1]);
            *(float2*)(outp + (size_t)r * DIMV + c) = o;
        }
    }
}

// ---------------------------------------------------------------------------
// Batched NT GEMM for dots:  C[r,c] = scale * A[r,:64] . B[c,:64], masked.
// ---------------------------------------------------------------------------
__global__ void __launch_bounds__(256, 2) dots_gemm(
    const float* __restrict__ Aall, const float* __restrict__ Ball,
    const int* __restrict__ mask, float* __restrict__ outAll,
    int rowsC, int colsC, int mrs, int mcs)
{
    int bh = blockIdx.z;
    const float* A = Aall + (size_t)bh * rowsC * DD;
    const float* Bm = Ball + (size_t)bh * colsC * DD;
    const int* mk = mask + (size_t)bh * NSEQ * MSEQ;
    float* outp = outAll + (size_t)bh * rowsC * colsC;

    __shared__ __align__(16) float As[16][132];
    __shared__ __align__(16) float Bs[16][132];
    int tid = threadIdx.x;
    int rowBase = blockIdx.y * 128;
    int colBase = blockIdx.x * 128;
    int trow = tid >> 4, tcol = tid & 15;
    u64t acc[8][4];
#pragma unroll
    for (int i = 0; i < 8; i++)
#pragma unroll
        for (int j = 0; j < 4; j++) acc[i][j] = 0ull;

    int aRow = tid >> 2, aCol = (tid & 3) << 2;

    for (int kk = 0; kk < DD; kk += 16) {
#pragma unroll
        for (int it = 0; it < 2; ++it) {
            float4 v = *(const float4*)(A + (size_t)(rowBase + aRow + it * 64) * DD + kk + aCol);
            As[aCol + 0][aRow + it * 64] = v.x;
            As[aCol + 1][aRow + it * 64] = v.y;
            As[aCol + 2][aRow + it * 64] = v.z;
            As[aCol + 3][aRow + it * 64] = v.w;
            float4 w = *(const float4*)(Bm + (size_t)(colBase + aRow + it * 64) * DD + kk + aCol);
            Bs[aCol + 0][aRow + it * 64] = w.x;
            Bs[aCol + 1][aRow + it * 64] = w.y;
            Bs[aCol + 2][aRow + it * 64] = w.z;
            Bs[aCol + 3][aRow + it * 64] = w.w;
        }
        __syncthreads();
        GEMM_INNER_16(As, Bs, acc)
        __syncthreads();
    }

#pragma unroll
    for (int i = 0; i < 8; i++) {
        int r = rowBase + trow * 8 + i;
#pragma unroll
        for (int j = 0; j < 4; j++) {
            int c = colBase + tcol * 8 + 2 * j;
            float v0, v1;
            UNPACK_X2(v0, v1, acc[i][j]);
            v0 *= SCALEF; v1 *= SCALEF;
            if (mk[r * mrs + c * mcs]) v0 = NEGF;
            if (mk[r * mrs + (c + 1) * mcs]) v1 = NEGF;
            *(float2*)(outp + (size_t)r * colsC + c) = make_float2(v0, v1);
        }
    }
}

// ---------------------------------------------------------------------------
// Batched AV GEMM: C[rowsC,64] = A[rowsC,K] @ V[K,64]; write merged [b,s,h*64+d]
// ---------------------------------------------------------------------------
__global__ void __launch_bounds__(256, 2) av_gemm(
    const float* __restrict__ Aall, const float* __restrict__ Vall,
    float* __restrict__ outp, int rowsC, int Kdim, int seq)
{
    int bh = blockIdx.y;
    int b = bh / HH, h = bh % HH;
    const float* A = Aall + (size_t)bh * rowsC * Kdim;
    const float* V = Vall + (size_t)bh * Kdim * DD;

    __shared__ __align__(16) float As[16][132];
    __shared__ __align__(16) float Bs[16][68];
    int tid = threadIdx.x;
    int rowBase = blockIdx.x * 128;
    int trow = tid >> 4, tcol = tid & 15;
    u64t acc[8][2];
#pragma unroll
    for (int i = 0; i < 8; i++)
#pragma unroll
        for (int j = 0; j < 2; j++) acc[i][j] = 0ull;

    int aRow = tid >> 2, aCol = (tid & 3) << 2;
    int vRow = tid >> 4, vCol = (tid & 15) << 2;

    for (int kk = 0; kk < Kdim; kk += 16) {
#pragma unroll
        for (int it = 0; it < 2; ++it) {
            float4 v = *(const float4*)(A + (size_t)(rowBase + aRow + it * 64) * Kdim + kk + aCol);
            As[aCol + 0][aRow + it * 64] = v.x;
            As[aCol + 1][aRow + it * 64] = v.y;
            As[aCol + 2][aRow + it * 64] = v.z;
            As[aCol + 3][aRow + it * 64] = v.w;
        }
        {
            float4 v = *(const float4*)(V + (size_t)(kk + vRow) * DD + vCol);
            *(float4*)&Bs[vRow][vCol] = v;
        }
        __syncthreads();
#pragma unroll
        for (int k = 0; k < 16; k++) {
            float4 ra0 = *(const float4*)&As[k][trow * 8];
            float4 ra1 = *(const float4*)&As[k][trow * 8 + 4];
            longlong2 rb = *(const longlong2*)&Bs[k][tcol * 4];
            u64t rbp[2] = {(u64t)rb.x, (u64t)rb.y};
            float a_s[8] = {ra0.x, ra0.y, ra0.z, ra0.w,
                            ra1.x, ra1.y, ra1.z, ra1.w};
#pragma unroll
            for (int i = 0; i < 8; i++) {
                u64t ap; PACK_DUP(ap, a_s[i]);
#pragma unroll
                for (int j = 0; j < 2; j++) FMA_X2(acc[i][j], ap, rbp[j], acc[i][j]);
            }
        }
        __syncthreads();
    }

#pragma unroll
    for (int i = 0; i < 8; i++) {
        int r = rowBase + trow * 8 + i;
#pragma unroll
        for (int j = 0; j < 2; j++) {
            int d = tcol * 4 + 2 * j;
            float v0, v1;
            UNPACK_X2(v0, v1, acc[i][j]);
            *(float2*)(outp + (size_t)(b * seq + r) * DIMV + h * 64 + d) = make_float2(v0, v1);
        }
    }
}

// ---------------------------------------------------------------------------
// Softmax stats, branch 1: per row (length 512): max, sum exp, sum exp(24*)
// ---------------------------------------------------------------------------
__global__ void __launch_bounds__(256) stats1_kernel()
{
    int gw = (blockIdx.x * 256 + threadIdx.x) >> 5;
    int lane = threadIdx.x & 31;
    const float* row = g_dots1 + (size_t)gw * MSEQ;
    float v[16], m = -3.4e38f;
#pragma unroll
    for (int i = 0; i < 16; i++) { v[i] = row[lane + 32 * i]; m = fmaxf(m, v[i]); }
#pragma unroll
    for (int o = 16; o > 0; o >>= 1) m = fmaxf(m, __shfl_xor_sync(0xffffffffu, m, o));
    float s = 0.f, sh = 0.f;
#pragma unroll
    for (int i = 0; i < 16; i++) {
        float t = v[i] - m;
        s += __expf(t);
        sh += __expf(TEMPF * t);
    }
#pragma unroll
    for (int o = 16; o > 0; o >>= 1) {
        s  += __shfl_xor_sync(0xffffffffu, s, o);
        sh += __shfl_xor_sync(0xffffffffu, sh, o);
    }
    if (lane == 0) { g_mx1[gw] = m; g_s1[gw] = s; g_sh1[gw] = sh; }
}

// ---------------------------------------------------------------------------
// Branch-1 apply: 32x32 tile transpose.
//   attn[n,m]   = exp(d-mx)/s1 * krd[m,n]      -> overwrite g_dots1 (n-major)
//   hot [m,n]   = exp(24(d-mx))/sh * krd[m,n]  -> out4 [b,h,m,n]
// ---------------------------------------------------------------------------
__global__ void apply1_kernel(const float* __restrict__ krd, float* __restrict__ out4)
{
    __shared__ float sd[32][33];
    __shared__ float sk[32][33];
    __shared__ float smx[32], ss1[32], ssh[32];
    int bh = blockIdx.z;
    int n0 = blockIdx.x * 32, m0 = blockIdx.y * 32;
    int tx = threadIdx.x, ty = threadIdx.y;
    const float* dbase = g_dots1 + (size_t)bh * NSEQ * MSEQ;
    const float* kbase = krd + (size_t)bh * MSEQ * NSEQ;

    int t = ty * 32 + tx;
    if (t < 32) {
        smx[t] = g_mx1[bh * NSEQ + n0 + t];
        ss1[t] = g_s1 [bh * NSEQ + n0 + t];
        ssh[t] = g_sh1[bh * NSEQ + n0 + t];
    }
#pragma unroll
    for (int it = 0; it < 4; it++) {
        int l = ty + 8 * it;
        sd[l][tx] = dbase[(size_t)(n0 + l) * MSEQ + m0 + tx];
        sk[l][tx] = kbase[(size_t)(m0 + l) * NSEQ + n0 + tx];
    }
    __syncthreads();

#pragma unroll
    for (int it = 0; it < 4; it++) {
        int nl = ty + 8 * it;
        float e = __expf(sd[nl][tx] - smx[nl]);
        float a = e / ss1[nl] * sk[tx][nl];
        g_dots1[(size_t)bh * NSEQ * MSEQ + (size_t)(n0 + nl) * MSEQ + m0 + tx] = a;
    }
#pragma unroll
    for (int it = 0; it < 4; it++) {
        int ml = ty + 8 * it;
        float e = __expf(TEMPF * (sd[tx][ml] - smx[tx]));
        float hv = e / ssh[tx] * sk[ml][tx];
        out4[(size_t)bh * MSEQ * NSEQ + (size_t)(m0 + ml) * NSEQ + n0 + tx] = hv;
    }
}

// ---------------------------------------------------------------------------
// Branch-2 fused softmax + krd apply: one block per row (length 2048)
// Reads dots2 ONCE, writes k_attn in place.
// ---------------------------------------------------------------------------
__global__ void __launch_bounds__(256) softmax2_kernel(const float* __restrict__ krd)
{
    __shared__ float red[8];
    int row = blockIdx.x;
    int tid = threadIdx.x;
    int lane = tid & 31, warp = tid >> 5;
    float* drow = g_dots2 + (size_t)row * NSEQ;
    const float* krow = krd + (size_t)row * NSEQ;

    float4 v0 = ((const float4*)drow)[tid];
    float4 v1 = ((const float4*)drow)[tid + 256];
    float m = fmaxf(fmaxf(fmaxf(v0.x, v0.y), fmaxf(v0.z, v0.w)),
                    fmaxf(fmaxf(v1.x, v1.y), fmaxf(v1.z, v1.w)));
#pragma unroll
    for (int o = 16; o > 0; o >>= 1) m = fmaxf(m, __shfl_xor_sync(0xffffffffu, m, o));
    if (lane == 0) red[warp] = m;
    __syncthreads();
    m = red[lane & 7];
#pragma unroll
    for (int o = 4; o > 0; o >>= 1) m = fmaxf(m, __shfl_xor_sync(0xffffffffu, m, o));

    float e0x = __expf(v0.x - m), e0y = __expf(v0.y - m), e0z = __expf(v0.z - m), e0w = __expf(v0.w - m);
    float e1x = __expf(v1.x - m), e1y = __expf(v1.y - m), e1z = __expf(v1.z - m), e1w = __expf(v1.w - m);
    float s = e0x + e0y + e0z + e0w + e1x + e1y + e1z + e1w;
#pragma unroll
    for (int o = 16; o > 0; o >>= 1) s += __shfl_xor_sync(0xffffffffu, s, o);
    __syncthreads();
    if (lane == 0) red[warp] = s;
    __syncthreads();
    s = red[lane & 7];
#pragma unroll
    for (int o = 4; o > 0; o >>= 1) s += __shfl_xor_sync(0xffffffffu, s, o);
    float inv = 1.f / s;

    float4 k0 = ((const float4*)krow)[tid];
    float4 k1 = ((const float4*)krow)[tid + 256];
    float4 o0 = make_float4(e0x * inv * k0.x, e0y * inv * k0.y, e0z * inv * k0.z, e0w * inv * k0.w);
    float4 o1 = make_float4(e1x * inv * k1.x, e1y * inv * k1.y, e1z * inv * k1.z, e1w * inv * k1.w);
    ((float4*)drow)[tid] = o0;
    ((float4*)drow)[tid + 256] = o1;
}

// ---------------------------------------------------------------------------
// Branch 3: cluster query vs kernel keys. One block per (b,h).
// ---------------------------------------------------------------------------
__global__ void __launch_bounds__(256) cluster_kernel(const int* __restrict__ mask)
{
    int bh = blockIdx.x;
    int b = bh / HH, h = bh % HH;
    __shared__ float q[64];
    __shared__ float p[512];
    __shared__ float red[256];
    int tid = threadIdx.x;
    const float* cq = g_cq + bh * 64;
    const float* kk = g_kk + (size_t)bh * MSEQ * DD;
    const float* kv = g_kv + (size_t)bh * MSEQ * DD;

    if (tid < 64) q[tid] = cq[tid];
    __syncthreads();

    for (int m = tid; m < MSEQ; m += 256) {
        float acc = 0.f;
#pragma unroll
        for (int d = 0; d < 64; d++) acc += q[d] * kk[m * 64 + d];
        acc *= SCALEF;
        if (mask[(size_t)bh * NSEQ * MSEQ + m]) acc = NEGF;
        p[m] = acc;
    }
    __syncthreads();

    red[tid] = fmaxf(p[tid], p[tid + 256]);
    __syncthreads();
    for (int s = 128; s > 0; s >>= 1) {
        if (tid < s) red[tid] = fmaxf(red[tid], red[tid + s]);
        __syncthreads();
    }
    float mx = red[0];
    __syncthreads();

    float e0 = __expf(p[tid] - mx), e1 = __expf(p[tid + 256] - mx);
    p[tid] = e0; p[tid + 256] = e1;
    red[tid] = e0 + e1;
    __syncthreads();
    for (int s = 128; s > 0; s >>= 1) {
        if (tid < s) red[tid] += red[tid + s];
        __syncthreads();
    }
    float inv = 1.f / red[0];
    __syncthreads();

    int d = tid & 63, part = tid >> 6;
    float acc = 0.f;
    for (int m = part * 128; m < part * 128 + 128; m++) acc += p[m] * kv[m * 64 + d];
    red[tid] = acc * inv;
    __syncthreads();
    if (part == 0)
        g_cO[b * DIMV + h * 64 + d] = red[d] + red[64 + d] + red[128 + d] + red[192 + d];
}

// ---------------------------------------------------------------------------
// Host launcher
// ---------------------------------------------------------------------------
extern "C" void kernel_launch(void* const* d_in, const int* in_sizes, int n_in,
                              void* d_out, int out_size)
{
    const float* x    = (const float*)d_in[0];
    const float* kx   = (const float*)d_in[1];
    const float* krd  = (const float*)d_in[2];
    const float* clst = (const float*)d_in[3];
    const int*   mask = (const int*)d_in[4];
    const float* Wqkv = (const float*)d_in[5];
    const float* Wout = (const float*)d_in[6];
    const float* bout = (const float*)d_in[7];
    float* out  = (float*)d_out;
    float* out1 = out + OUT1_OFF;
    float* out2 = out + OUT2_OFF;
    float* out3 = out + OUT3_OFF;
    float* out4 = out + OUT4_OFF;

    float *p_tq, *p_tk, *p_tv, *p_kq, *p_kk, *p_kv, *p_cq, *p_ck, *p_cv;
    float *p_d1, *p_d2, *p_attO, *p_kO, *p_cO;
    cudaGetSymbolAddress((void**)&p_tq, g_tq);
    cudaGetSymbolAddress((void**)&p_tk, g_tk);
    cudaGetSymbolAddress((void**)&p_tv, g_tv);
    cudaGetSymbolAddress((void**)&p_kq, g_kq);
    cudaGetSymbolAddress((void**)&p_kk, g_kk);
    cudaGetSymbolAddress((void**)&p_kv, g_kv);
    cudaGetSymbolAddress((void**)&p_cq, g_cq);
    cudaGetSymbolAddress((void**)&p_ck, g_ck);
    cudaGetSymbolAddress((void**)&p_cv, g_cv);
    cudaGetSymbolAddress((void**)&p_d1, g_dots1);
    cudaGetSymbolAddress((void**)&p_d2, g_dots2);
    cudaGetSymbolAddress((void**)&p_attO, g_attO);
    cudaGetSymbolAddress((void**)&p_kO, g_kO);
    cudaGetSymbolAddress((void**)&p_cO, g_cO);

    // 1) QKV projections
    qkv_gemm<<<dim3(TRIPLE / 128, (BB * NSEQ) / 128), 256>>>(x, Wqkv, p_tq, p_tk, p_tv, BB * NSEQ, NSEQ);
    qkv_gemm<<<dim3(TRIPLE / 128, (BB * MSEQ) / 128), 256>>>(kx, Wqkv, p_kq, p_kk, p_kv, BB * MSEQ, MSEQ);
    qkv_gemm<<<dim3(TRIPLE / 128, 1), 256>>>(clst, Wqkv, p_cq, p_ck, p_cv, BB, 1);

    // 2) dots (masked + scaled)
    dots_gemm<<<dim3(MSEQ / 128, NSEQ / 128, BH), 256>>>(p_tq, p_kk, mask, p_d1,
                                                         NSEQ, MSEQ, MSEQ, 1);
    dots_gemm<<<dim3(NSEQ / 128, MSEQ / 128, BH), 256>>>(p_kq, p_tk, mask, p_d2,
                                                         MSEQ, NSEQ, 1, MSEQ);

    // 3) softmax stats (branch 1) + fused softmax (branch 2)
    stats1_kernel<<<(BH * NSEQ) / 8, 256>>>();
    softmax2_kernel<<<BH * MSEQ, 256>>>(krd);

    // 4) branch-1 apply (attn / attn_hot)
    apply1_kernel<<<dim3(NSEQ / 32, MSEQ / 32, BH), dim3(32, 8)>>>(krd, out4);

    // 5) attention-value GEMMs
    av_gemm<<<dim3(NSEQ / 128, BH), 256>>>(p_d1, p_kv, p_attO, NSEQ, MSEQ, NSEQ);
    av_gemm<<<dim3(MSEQ / 128, BH), 256>>>(p_d2, p_tv, p_kO, MSEQ, NSEQ, MSEQ);

    // 6) cluster branch
    cluster_kernel<<<BH, 256>>>(mask);

    // 7) output projections
    proj_gemm<<<dim3(DIMV / 128, (BB * NSEQ) / 128), 256>>>(p_attO, Wout, bout, out1, BB * NSEQ);
    proj_gemm<<<dim3(DIMV / 128, (BB * MSEQ) / 128), 256>>>(p_kO, Wout, bout, out2, BB * MSEQ);
    proj_gemm<<<dim3(DIMV / 128, 1), 256>>>(p_cO, Wout, bout, out3, BB);
}

// round 15
// speedup vs baseline: 1.6347x; 1.0562x over previous
#include <cuda_runtime.h>
#include <cstdint>

// ---------------------------------------------------------------------------
// Problem constants
// ---------------------------------------------------------------------------
#define BB    4
#define NSEQ  2048
#define MSEQ  512
#define HH    12
#define DD    64
#define DIMV  768
#define TRIPLE 2304
#define BH    (BB*HH)          // 48
#define SCALEF 0.125f
#define TEMPF  24.0f
#define NEGF  (-1e9f)

// Output segment offsets (floats)
#define OUT1_OFF 0
#define OUT2_OFF (BB*NSEQ*DIMV)                 // 6291456
#define OUT3_OFF (OUT2_OFF + BB*MSEQ*DIMV)      // 7864320
#define OUT4_OFF (OUT3_OFF + BB*DIMV)           // 7867392

// ---------------------------------------------------------------------------
// Packed f32x2 helpers (FFMA2 — only reachable via PTX)
// ---------------------------------------------------------------------------
#define FMA_X2(d, a, b, c) \
    asm("fma.rn.f32x2 %0, %1, %2, %3;" : "=l"(d) : "l"(a), "l"(b), "l"(c))
#define PACK_DUP(p, f) \
    asm("mov.b64 %0, {%1, %2};" : "=l"(p) : "f"(f), "f"(f))
#define UNPACK_X2(lo, hi, p) \
    asm("mov.b64 {%0, %1}, %2;" : "=f"(lo), "=f"(hi) : "l"(p))

typedef unsigned long long u64t;

// ---------------------------------------------------------------------------
// tf32 split + mma.sync helpers (3xTF32 split-precision GEMM)
// ---------------------------------------------------------------------------
__device__ __forceinline__ void tf32_split(float x, uint32_t& hi, uint32_t& lo)
{
    asm("cvt.rna.tf32.f32 %0, %1;" : "=r"(hi) : "f"(x));
    float r = x - __uint_as_float(hi);
    asm("cvt.rna.tf32.f32 %0, %1;" : "=r"(lo) : "f"(r));
}

#define MMA_TF32(d, a0, a1, a2, a3, b0, b1)                                  \
    asm volatile("mma.sync.aligned.m16n8k8.row.col.f32.tf32.tf32.f32 "       \
        "{%0,%1,%2,%3}, {%4,%5,%6,%7}, {%8,%9}, {%0,%1,%2,%3};"              \
        : "+f"(d[0]), "+f"(d[1]), "+f"(d[2]), "+f"(d[3])                     \
        : "r"(a0), "r"(a1), "r"(a2), "r"(a3), "r"(b0), "r"(b1))

// ---------------------------------------------------------------------------
// Device scratch (no cudaMalloc allowed)
// ---------------------------------------------------------------------------
__device__ float g_tq[BB*HH*NSEQ*DD];
__device__ float g_tk[BB*HH*NSEQ*DD];
__device__ float g_tv[BB*HH*NSEQ*DD];
__device__ float g_kq[BB*HH*MSEQ*DD];
__device__ float g_kk[BB*HH*MSEQ*DD];
__device__ float g_kv[BB*HH*MSEQ*DD];
__device__ float g_cq[BB*HH*DD];
__device__ float g_ck[BB*HH*DD];
__device__ float g_cv[BB*HH*DD];
__device__ float g_dots1[BB*HH*NSEQ*MSEQ];   // later overwritten with attn
__device__ float g_dots2[BB*HH*MSEQ*NSEQ];   // later overwritten with k_attn
__device__ float g_attO[BB*NSEQ*DIMV];
__device__ float g_kO[BB*MSEQ*DIMV];
__device__ float g_cO[BB*DIMV];
__device__ float g_mx1[BB*HH*NSEQ];
__device__ float g_s1 [BB*HH*NSEQ];
__device__ float g_sh1[BB*HH*NSEQ];

// Inner-loop body shared by the 128-wide SIMT GEMMs.
#define GEMM_INNER_16(As, Bs, acc)                                         \
    _Pragma("unroll")                                                      \
    for (int k = 0; k < 16; k++) {                                         \
        float4 ra0 = *(const float4*)&As[k][trow * 8];                     \
        float4 ra1 = *(const float4*)&As[k][trow * 8 + 4];                 \
        longlong2 rb0 = *(const longlong2*)&Bs[k][tcol * 8];               \
        longlong2 rb1 = *(const longlong2*)&Bs[k][tcol * 8 + 4];           \
        u64t rbp[4] = {(u64t)rb0.x, (u64t)rb0.y, (u64t)rb1.x, (u64t)rb1.y};\
        float a_s[8] = {ra0.x, ra0.y, ra0.z, ra0.w,                        \
                        ra1.x, ra1.y, ra1.z, ra1.w};                       \
        _Pragma("unroll")                                                  \
        for (int i = 0; i < 8; i++) {                                      \
            u64t ap; PACK_DUP(ap, a_s[i]);                                 \
            _Pragma("unroll")                                              \
            for (int j = 0; j < 4; j++) FMA_X2(acc[i][j], ap, rbp[j], acc[i][j]); \
        }                                                                  \
    }

// ---------------------------------------------------------------------------
// QKV GEMM:  C[rows,2304] = A[rows,768] @ W[768,2304], scatter to q/k/v
// ---------------------------------------------------------------------------
__global__ void __launch_bounds__(256, 2) qkv_gemm(
    const float* __restrict__ A, const float* __restrict__ W,
    float* __restrict__ oq, float* __restrict__ ok2, float* __restrict__ ov,
    int rows, int seq)
{
    __shared__ __align__(16) float As[16][132];
    __shared__ __align__(16) float Bs[16][132];
    int tid = threadIdx.x;
    int rowBase = blockIdx.y * 128;
    int colBase = blockIdx.x * 128;
    int trow = tid >> 4, tcol = tid & 15;
    u64t acc[8][4];
#pragma unroll
    for (int i = 0; i < 8; i++)
#pragma unroll
        for (int j = 0; j < 4; j++) acc[i][j] = 0ull;

    int aRow = tid >> 2, aCol = (tid & 3) << 2;
    int bRow = tid >> 5, bCol = (tid & 31) << 2;

    for (int kk = 0; kk < DIMV; kk += 16) {
#pragma unroll
        for (int it = 0; it < 2; ++it) {
            int r = rowBase + aRow + it * 64;
            float4 v = make_float4(0.f, 0.f, 0.f, 0.f);
            if (r < rows) v = *(const float4*)(A + (size_t)r * DIMV + kk + aCol);
            As[aCol + 0][aRow + it * 64] = v.x;
            As[aCol + 1][aRow + it * 64] = v.y;
            As[aCol + 2][aRow + it * 64] = v.z;
            As[aCol + 3][aRow + it * 64] = v.w;
        }
#pragma unroll
        for (int it = 0; it < 2; ++it) {
            int kr = bRow + it * 8;
            float4 v = *(const float4*)(W + (size_t)(kk + kr) * TRIPLE + colBase + bCol);
            *(float4*)&Bs[kr][bCol] = v;
        }
        __syncthreads();
        GEMM_INNER_16(As, Bs, acc)
        __syncthreads();
    }

#pragma unroll
    for (int i = 0; i < 8; i++) {
        int r = rowBase + trow * 8 + i;
        if (r >= rows) break;
        int b = r / seq, s = r % seq;
#pragma unroll
        for (int j = 0; j < 4; j++) {
            float v0, v1;
            UNPACK_X2(v0, v1, acc[i][j]);
#pragma unroll
            for (int u = 0; u < 2; u++) {
                int c = colBase + tcol * 8 + 2 * j + u;
                float v = u ? v1 : v0;
                int part = c / DIMV, cc = c % DIMV;
                int h = cc >> 6, d = cc & 63;
                int idx = ((b * HH + h) * seq + s) * DD + d;
                if (part == 0) oq[idx] = v;
                else if (part == 1) ok2[idx] = v;
                else ov[idx] = v;
            }
        }
    }
}

// ---------------------------------------------------------------------------
// Projection GEMM: out[rows,768] = A[rows,768] @ W[768,768] + bias
// ---------------------------------------------------------------------------
__global__ void __launch_bounds__(256, 2) proj_gemm(
    const float* __restrict__ A, const float* __restrict__ W,
    const float* __restrict__ bias, float* __restrict__ outp, int rows)
{
    __shared__ __align__(16) float As[16][132];
    __shared__ __align__(16) float Bs[16][132];
    int tid = threadIdx.x;
    int rowBase = blockIdx.y * 128;
    int colBase = blockIdx.x * 128;
    int trow = tid >> 4, tcol = tid & 15;
    u64t acc[8][4];
#pragma unroll
    for (int i = 0; i < 8; i++)
#pragma unroll
        for (int j = 0; j < 4; j++) acc[i][j] = 0ull;

    int aRow = tid >> 2, aCol = (tid & 3) << 2;
    int bRow = tid >> 5, bCol = (tid & 31) << 2;

    for (int kk = 0; kk < DIMV; kk += 16) {
#pragma unroll
        for (int it = 0; it < 2; ++it) {
            int r = rowBase + aRow + it * 64;
            float4 v = make_float4(0.f, 0.f, 0.f, 0.f);
            if (r < rows) v = *(const float4*)(A + (size_t)r * DIMV + kk + aCol);
            As[aCol + 0][aRow + it * 64] = v.x;
            As[aCol + 1][aRow + it * 64] = v.y;
            As[aCol + 2][aRow + it * 64] = v.z;
            As[aCol + 3][aRow + it * 64] = v.w;
        }
#pragma unroll
        for (int it = 0; it < 2; ++it) {
            int kr = bRow + it * 8;
            float4 v = *(const float4*)(W + (size_t)(kk + kr) * DIMV + colBase + bCol);
            *(float4*)&Bs[kr][bCol] = v;
        }
        __syncthreads();
        GEMM_INNER_16(As, Bs, acc)
        __syncthreads();
    }

#pragma unroll
    for (int i = 0; i < 8; i++) {
        int r = rowBase + trow * 8 + i;
        if (r >= rows) break;
#pragma unroll
        for (int j = 0; j < 4; j++) {
            int c = colBase + tcol * 8 + 2 * j;
            float v0, v1;
            UNPACK_X2(v0, v1, acc[i][j]);
            float2 o = make_float2(v0 + bias[c], v1 + bias[c + 1]);
            *(float2*)(outp + (size_t)r * DIMV + c) = o;
        }
    }
}

// ---------------------------------------------------------------------------
// Batched NT GEMM for dots via 3xTF32 mma.sync (tensor cores).
//   C[r,c] = scale * A[r,:64] . B[c,:64], masked.
// 8 warps as 2(M) x 4(N); warp tile 64x32 = 4x4 m16n8k8 tiles.
// ---------------------------------------------------------------------------
__global__ void __launch_bounds__(256, 2) dots_gemm(
    const float* __restrict__ Aall, const float* __restrict__ Ball,
    const int* __restrict__ mask, float* __restrict__ outAll,
    int rowsC, int colsC, int mrs, int mcs)
{
    int bh = blockIdx.z;
    const float* A = Aall + (size_t)bh * rowsC * DD;
    const float* Bm = Ball + (size_t)bh * colsC * DD;
    const int* mk = mask + (size_t)bh * NSEQ * MSEQ;
    float* outp = outAll + (size_t)bh * rowsC * colsC;

    __shared__ __align__(16) float As[16][132];
    __shared__ __align__(16) float Bs[16][132];
    int tid = threadIdx.x;
    int rowBase = blockIdx.y * 128;
    int colBase = blockIdx.x * 128;
    int warp = tid >> 5, lane = tid & 31;
    int wm = warp >> 2, wn = warp & 3;     // 2 x 4 warp grid
    int g = lane >> 2, tig = lane & 3;     // mma group/thread-in-group

    float acc[4][4][4];
#pragma unroll
    for (int mt = 0; mt < 4; mt++)
#pragma unroll
        for (int nt = 0; nt < 4; nt++)
#pragma unroll
            for (int c = 0; c < 4; c++) acc[mt][nt][c] = 0.f;

    int aRow = tid >> 2, aCol = (tid & 3) << 2;

    for (int kk = 0; kk < DD; kk += 16) {
        // stage A,B tiles transposed to k-major [k][seq] (same as SIMT version)
#pragma unroll
        for (int it = 0; it < 2; ++it) {
            float4 v = *(const float4*)(A + (size_t)(rowBase + aRow + it * 64) * DD + kk + aCol);
            As[aCol + 0][aRow + it * 64] = v.x;
            As[aCol + 1][aRow + it * 64] = v.y;
            As[aCol + 2][aRow + it * 64] = v.z;
            As[aCol + 3][aRow + it * 64] = v.w;
            float4 w = *(const float4*)(Bm + (size_t)(colBase + aRow + it * 64) * DD + kk + aCol);
            Bs[aCol + 0][aRow + it * 64] = w.x;
            Bs[aCol + 1][aRow + it * 64] = w.y;
            Bs[aCol + 2][aRow + it * 64] = w.z;
            Bs[aCol + 3][aRow + it * 64] = w.w;
        }
        __syncthreads();

#pragma unroll
        for (int kc = 0; kc < 2; kc++) {
            int kb = kc * 8;
            // B fragments for 4 n-tiles: b0=(k=tig, n=g), b1=(k=tig+4, n=g)
            uint32_t bhi[4][2], blo[4][2];
#pragma unroll
            for (int nt = 0; nt < 4; nt++) {
                int cb = wn * 32 + nt * 8 + g;
                tf32_split(Bs[kb + tig][cb],     bhi[nt][0], blo[nt][0]);
                tf32_split(Bs[kb + tig + 4][cb], bhi[nt][1], blo[nt][1]);
            }
#pragma unroll
            for (int mt = 0; mt < 4; mt++) {
                int rb = wm * 64 + mt * 16;
                // A fragments: a0=(m=g,k=tig) a1=(m=g+8,k=tig) a2=(m=g,k=tig+4) a3=(m=g+8,k=tig+4)
                uint32_t ahi[4], alo[4];
                tf32_split(As[kb + tig][rb + g],         ahi[0], alo[0]);
                tf32_split(As[kb + tig][rb + g + 8],     ahi[1], alo[1]);
                tf32_split(As[kb + tig + 4][rb + g],     ahi[2], alo[2]);
                tf32_split(As[kb + tig + 4][rb + g + 8], ahi[3], alo[3]);
#pragma unroll
                for (int nt = 0; nt < 4; nt++) {
                    MMA_TF32(acc[mt][nt], ahi[0], ahi[1], ahi[2], ahi[3], bhi[nt][0], bhi[nt][1]);
                    MMA_TF32(acc[mt][nt], ahi[0], ahi[1], ahi[2], ahi[3], blo[nt][0], blo[nt][1]);
                    MMA_TF32(acc[mt][nt], alo[0], alo[1], alo[2], alo[3], bhi[nt][0], bhi[nt][1]);
                }
            }
        }
        __syncthreads();
    }

    // epilogue: c0=(m=g, n=2tig), c1=(m=g, n=2tig+1), c2/c3 at m=g+8
#pragma unroll
    for (int mt = 0; mt < 4; mt++) {
#pragma unroll
        for (int nt = 0; nt < 4; nt++) {
            int r0 = rowBase + wm * 64 + mt * 16 + g;
            int r1 = r0 + 8;
            int c0 = colBase + wn * 32 + nt * 8 + 2 * tig;
            float v0 = acc[mt][nt][0] * SCALEF;
            float v1 = acc[mt][nt][1] * SCALEF;
            float v2 = acc[mt][nt][2] * SCALEF;
            float v3 = acc[mt][nt][3] * SCALEF;
            if (mk[r0 * mrs + c0 * mcs]) v0 = NEGF;
            if (mk[r0 * mrs + (c0 + 1) * mcs]) v1 = NEGF;
            if (mk[r1 * mrs + c0 * mcs]) v2 = NEGF;
            if (mk[r1 * mrs + (c0 + 1) * mcs]) v3 = NEGF;
            *(float2*)(outp + (size_t)r0 * colsC + c0) = make_float2(v0, v1);
            *(float2*)(outp + (size_t)r1 * colsC + c0) = make_float2(v2, v3);
        }
    }
}

// ---------------------------------------------------------------------------
// Batched AV GEMM: C[rowsC,64] = A[rowsC,K] @ V[K,64]; write merged [b,s,h*64+d]
// ---------------------------------------------------------------------------
__global__ void __launch_bounds__(256, 2) av_gemm(
    const float* __restrict__ Aall, const float* __restrict__ Vall,
    float* __restrict__ outp, int rowsC, int Kdim, int seq)
{
    int bh = blockIdx.y;
    int b = bh / HH, h = bh % HH;
    const float* A = Aall + (size_t)bh * rowsC * Kdim;
    const float* V = Vall + (size_t)bh * Kdim * DD;

    __shared__ __align__(16) float As[16][132];
    __shared__ __align__(16) float Bs[16][68];
    int tid = threadIdx.x;
    int rowBase = blockIdx.x * 128;
    int trow = tid >> 4, tcol = tid & 15;
    u64t acc[8][2];
#pragma unroll
    for (int i = 0; i < 8; i++)
#pragma unroll
        for (int j = 0; j < 2; j++) acc[i][j] = 0ull;

    int aRow = tid >> 2, aCol = (tid & 3) << 2;
    int vRow = tid >> 4, vCol = (tid & 15) << 2;

    for (int kk = 0; kk < Kdim; kk += 16) {
#pragma unroll
        for (int it = 0; it < 2; ++it) {
            float4 v = *(const float4*)(A + (size_t)(rowBase + aRow + it * 64) * Kdim + kk + aCol);
            As[aCol + 0][aRow + it * 64] = v.x;
            As[aCol + 1][aRow + it * 64] = v.y;
            As[aCol + 2][aRow + it * 64] = v.z;
            As[aCol + 3][aRow + it * 64] = v.w;
        }
        {
            float4 v = *(const float4*)(V + (size_t)(kk + vRow) * DD + vCol);
            *(float4*)&Bs[vRow][vCol] = v;
        }
        __syncthreads();
#pragma unroll
        for (int k = 0; k < 16; k++) {
            float4 ra0 = *(const float4*)&As[k][trow * 8];
            float4 ra1 = *(const float4*)&As[k][trow * 8 + 4];
            longlong2 rb = *(const longlong2*)&Bs[k][tcol * 4];
            u64t rbp[2] = {(u64t)rb.x, (u64t)rb.y};
            float a_s[8] = {ra0.x, ra0.y, ra0.z, ra0.w,
                            ra1.x, ra1.y, ra1.z, ra1.w};
#pragma unroll
            for (int i = 0; i < 8; i++) {
                u64t ap; PACK_DUP(ap, a_s[i]);
#pragma unroll
                for (int j = 0; j < 2; j++) FMA_X2(acc[i][j], ap, rbp[j], acc[i][j]);
            }
        }
        __syncthreads();
    }

#pragma unroll
    for (int i = 0; i < 8; i++) {
        int r = rowBase + trow * 8 + i;
#pragma unroll
        for (int j = 0; j < 2; j++) {
            int d = tcol * 4 + 2 * j;
            float v0, v1;
            UNPACK_X2(v0, v1, acc[i][j]);
            *(float2*)(outp + (size_t)(b * seq + r) * DIMV + h * 64 + d) = make_float2(v0, v1);
        }
    }
}

// ---------------------------------------------------------------------------
// Softmax stats, branch 1: per row (length 512): max, sum exp, sum exp(24*)
// ---------------------------------------------------------------------------
__global__ void __launch_bounds__(256) stats1_kernel()
{
    int gw = (blockIdx.x * 256 + threadIdx.x) >> 5;
    int lane = threadIdx.x & 31;
    const float* row = g_dots1 + (size_t)gw * MSEQ;
    float v[16], m = -3.4e38f;
#pragma unroll
    for (int i = 0; i < 16; i++) { v[i] = row[lane + 32 * i]; m = fmaxf(m, v[i]); }
#pragma unroll
    for (int o = 16; o > 0; o >>= 1) m = fmaxf(m, __shfl_xor_sync(0xffffffffu, m, o));
    float s = 0.f, sh = 0.f;
#pragma unroll
    for (int i = 0; i < 16; i++) {
        float t = v[i] - m;
        s += __expf(t);
        sh += __expf(TEMPF * t);
    }
#pragma unroll
    for (int o = 16; o > 0; o >>= 1) {
        s  += __shfl_xor_sync(0xffffffffu, s, o);
        sh += __shfl_xor_sync(0xffffffffu, sh, o);
    }
    if (lane == 0) { g_mx1[gw] = m; g_s1[gw] = s; g_sh1[gw] = sh; }
}

// ---------------------------------------------------------------------------
// Branch-1 apply: 32x32 tile transpose.
//   attn[n,m]   = exp(d-mx)/s1 * krd[m,n]      -> overwrite g_dots1 (n-major)
//   hot [m,n]   = exp(24(d-mx))/sh * krd[m,n]  -> out4 [b,h,m,n]
// ---------------------------------------------------------------------------
__global__ void apply1_kernel(const float* __restrict__ krd, float* __restrict__ out4)
{
    __shared__ float sd[32][33];
    __shared__ float sk[32][33];
    __shared__ float smx[32], ss1[32], ssh[32];
    int bh = blockIdx.z;
    int n0 = blockIdx.x * 32, m0 = blockIdx.y * 32;
    int tx = threadIdx.x, ty = threadIdx.y;
    const float* dbase = g_dots1 + (size_t)bh * NSEQ * MSEQ;
    const float* kbase = krd + (size_t)bh * MSEQ * NSEQ;

    int t = ty * 32 + tx;
    if (t < 32) {
        smx[t] = g_mx1[bh * NSEQ + n0 + t];
        ss1[t] = g_s1 [bh * NSEQ + n0 + t];
        ssh[t] = g_sh1[bh * NSEQ + n0 + t];
    }
#pragma unroll
    for (int it = 0; it < 4; it++) {
        int l = ty + 8 * it;
        sd[l][tx] = dbase[(size_t)(n0 + l) * MSEQ + m0 + tx];
        sk[l][tx] = kbase[(size_t)(m0 + l) * NSEQ + n0 + tx];
    }
    __syncthreads();

#pragma unroll
    for (int it = 0; it < 4; it++) {
        int nl = ty + 8 * it;
        float e = __expf(sd[nl][tx] - smx[nl]);
        float a = e / ss1[nl] * sk[tx][nl];
        g_dots1[(size_t)bh * NSEQ * MSEQ + (size_t)(n0 + nl) * MSEQ + m0 + tx] = a;
    }
#pragma unroll
    for (int it = 0; it < 4; it++) {
        int ml = ty + 8 * it;
        float e = __expf(TEMPF * (sd[tx][ml] - smx[tx]));
        float hv = e / ssh[tx] * sk[ml][tx];
        out4[(size_t)bh * MSEQ * NSEQ + (size_t)(m0 + ml) * NSEQ + n0 + tx] = hv;
    }
}

// ---------------------------------------------------------------------------
// Branch-2 fused softmax + krd apply: one block per row (length 2048)
// ---------------------------------------------------------------------------
__global__ void __launch_bounds__(256) softmax2_kernel(const float* __restrict__ krd)
{
    __shared__ float red[8];
    int row = blockIdx.x;
    int tid = threadIdx.x;
    int lane = tid & 31, warp = tid >> 5;
    float* drow = g_dots2 + (size_t)row * NSEQ;
    const float* krow = krd + (size_t)row * NSEQ;

    float4 v0 = ((const float4*)drow)[tid];
    float4 v1 = ((const float4*)drow)[tid + 256];
    float m = fmaxf(fmaxf(fmaxf(v0.x, v0.y), fmaxf(v0.z, v0.w)),
                    fmaxf(fmaxf(v1.x, v1.y), fmaxf(v1.z, v1.w)));
#pragma unroll
    for (int o = 16; o > 0; o >>= 1) m = fmaxf(m, __shfl_xor_sync(0xffffffffu, m, o));
    if (lane == 0) red[warp] = m;
    __syncthreads();
    m = red[lane & 7];
#pragma unroll
    for (int o = 4; o > 0; o >>= 1) m = fmaxf(m, __shfl_xor_sync(0xffffffffu, m, o));

    float e0x = __expf(v0.x - m), e0y = __expf(v0.y - m), e0z = __expf(v0.z - m), e0w = __expf(v0.w - m);
    float e1x = __expf(v1.x - m), e1y = __expf(v1.y - m), e1z = __expf(v1.z - m), e1w = __expf(v1.w - m);
    float s = e0x + e0y + e0z + e0w + e1x + e1y + e1z + e1w;
#pragma unroll
    for (int o = 16; o > 0; o >>= 1) s += __shfl_xor_sync(0xffffffffu, s, o);
    __syncthreads();
    if (lane == 0) red[warp] = s;
    __syncthreads();
    s = red[lane & 7];
#pragma unroll
    for (int o = 4; o > 0; o >>= 1) s += __shfl_xor_sync(0xffffffffu, s, o);
    float inv = 1.f / s;

    float4 k0 = ((const float4*)krow)[tid];
    float4 k1 = ((const float4*)krow)[tid + 256];
    float4 o0 = make_float4(e0x * inv * k0.x, e0y * inv * k0.y, e0z * inv * k0.z, e0w * inv * k0.w);
    float4 o1 = make_float4(e1x * inv * k1.x, e1y * inv * k1.y, e1z * inv * k1.z, e1w * inv * k1.w);
    ((float4*)drow)[tid] = o0;
    ((float4*)drow)[tid + 256] = o1;
}

// ---------------------------------------------------------------------------
// Branch 3: cluster query vs kernel keys. One block per (b,h).
// ---------------------------------------------------------------------------
__global__ void __launch_bounds__(256) cluster_kernel(const int* __restrict__ mask)
{
    int bh = blockIdx.x;
    int b = bh / HH, h = bh % HH;
    __shared__ float q[64];
    __shared__ float p[512];
    __shared__ float red[256];
    int tid = threadIdx.x;
    const float* cq = g_cq + bh * 64;
    const float* kk = g_kk + (size_t)bh * MSEQ * DD;
    const float* kv = g_kv + (size_t)bh * MSEQ * DD;

    if (tid < 64) q[tid] = cq[tid];
    __syncthreads();

    for (int m = tid; m < MSEQ; m += 256) {
        float acc = 0.f;
#pragma unroll
        for (int d = 0; d < 64; d++) acc += q[d] * kk[m * 64 + d];
        acc *= SCALEF;
        if (mask[(size_t)bh * NSEQ * MSEQ + m]) acc = NEGF;
        p[m] = acc;
    }
    __syncthreads();

    red[tid] = fmaxf(p[tid], p[tid + 256]);
    __syncthreads();
    for (int s = 128; s > 0; s >>= 1) {
        if (tid < s) red[tid] = fmaxf(red[tid], red[tid + s]);
        __syncthreads();
    }
    float mx = red[0];
    __syncthreads();

    float e0 = __expf(p[tid] - mx), e1 = __expf(p[tid + 256] - mx);
    p[tid] = e0; p[tid + 256] = e1;
    red[tid] = e0 + e1;
    __syncthreads();
    for (int s = 128; s > 0; s >>= 1) {
        if (tid < s) red[tid] += red[tid + s];
        __syncthreads();
    }
    float inv = 1.f / red[0];
    __syncthreads();

    int d = tid & 63, part = tid >> 6;
    float acc = 0.f;
    for (int m = part * 128; m < part * 128 + 128; m++) acc += p[m] * kv[m * 64 + d];
    red[tid] = acc * inv;
    __syncthreads();
    if (part == 0)
        g_cO[b * DIMV + h * 64 + d] = red[d] + red[64 + d] + red[128 + d] + red[192 + d];
}

// ---------------------------------------------------------------------------
// Host launcher
// ---------------------------------------------------------------------------
extern "C" void kernel_launch(void* const* d_in, const int* in_sizes, int n_in,
                              void* d_out, int out_size)
{
    const float* x    = (const float*)d_in[0];
    const float* kx   = (const float*)d_in[1];
    const float* krd  = (const float*)d_in[2];
    const float* clst = (const float*)d_in[3];
    const int*   mask = (const int*)d_in[4];
    const float* Wqkv = (const float*)d_in[5];
    const float* Wout = (const float*)d_in[6];
    const float* bout = (const float*)d_in[7];
    float* out  = (float*)d_out;
    float* out1 = out + OUT1_OFF;
    float* out2 = out + OUT2_OFF;
    float* out3 = out + OUT3_OFF;
    float* out4 = out + OUT4_OFF;

    float *p_tq, *p_tk, *p_tv, *p_kq, *p_kk, *p_kv, *p_cq, *p_ck, *p_cv;
    float *p_d1, *p_d2, *p_attO, *p_kO, *p_cO;
    cudaGetSymbolAddress((void**)&p_tq, g_tq);
    cudaGetSymbolAddress((void**)&p_tk, g_tk);
    cudaGetSymbolAddress((void**)&p_tv, g_tv);
    cudaGetSymbolAddress((void**)&p_kq, g_kq);
    cudaGetSymbolAddress((void**)&p_kk, g_kk);
    cudaGetSymbolAddress((void**)&p_kv, g_kv);
    cudaGetSymbolAddress((void**)&p_cq, g_cq);
    cudaGetSymbolAddress((void**)&p_ck, g_ck);
    cudaGetSymbolAddress((void**)&p_cv, g_cv);
    cudaGetSymbolAddress((void**)&p_d1, g_dots1);
    cudaGetSymbolAddress((void**)&p_d2, g_dots2);
    cudaGetSymbolAddress((void**)&p_attO, g_attO);
    cudaGetSymbolAddress((void**)&p_kO, g_kO);
    cudaGetSymbolAddress((void**)&p_cO, g_cO);

    // 1) QKV projections
    qkv_gemm<<<dim3(TRIPLE / 128, (BB * NSEQ) / 128), 256>>>(x, Wqkv, p_tq, p_tk, p_tv, BB * NSEQ, NSEQ);
    qkv_gemm<<<dim3(TRIPLE / 128, (BB * MSEQ) / 128), 256>>>(kx, Wqkv, p_kq, p_kk, p_kv, BB * MSEQ, MSEQ);
    qkv_gemm<<<dim3(TRIPLE / 128, 1), 256>>>(clst, Wqkv, p_cq, p_ck, p_cv, BB, 1);

    // 2) dots (masked + scaled) — 3xTF32 tensor-core path
    dots_gemm<<<dim3(MSEQ / 128, NSEQ / 128, BH), 256>>>(p_tq, p_kk, mask, p_d1,
                                                         NSEQ, MSEQ, MSEQ, 1);
    dots_gemm<<<dim3(NSEQ / 128, MSEQ / 128, BH), 256>>>(p_kq, p_tk, mask, p_d2,
                                                         MSEQ, NSEQ, 1, MSEQ);

    // 3) softmax stats (branch 1) + fused softmax (branch 2)
    stats1_kernel<<<(BH * NSEQ) / 8, 256>>>();
    softmax2_kernel<<<BH * MSEQ, 256>>>(krd);

    // 4) branch-1 apply (attn / attn_hot)
    apply1_kernel<<<dim3(NSEQ / 32, MSEQ / 32, BH), dim3(32, 8)>>>(krd, out4);

    // 5) attention-value GEMMs
    av_gemm<<<dim3(NSEQ / 128, BH), 256>>>(p_d1, p_kv, p_attO, NSEQ, MSEQ, NSEQ);
    av_gemm<<<dim3(MSEQ / 128, BH), 256>>>(p_d2, p_tv, p_kO, MSEQ, NSEQ, MSEQ);

    // 6) cluster branch
    cluster_kernel<<<BH, 256>>>(mask);

    // 7) output projections
    proj_gemm<<<dim3(DIMV / 128, (BB * NSEQ) / 128), 256>>>(p_attO, Wout, bout, out1, BB * NSEQ);
    proj_gemm<<<dim3(DIMV / 128, (BB * MSEQ) / 128), 256>>>(p_kO, Wout, bout, out2, BB * MSEQ);
    proj_gemm<<<dim3(DIMV / 128, 1), 256>>>(p_cO, Wout, bout, out3, BB);
}

// round 17
// speedup vs baseline: 1.8011x; 1.1017x over previous
#include <cuda_runtime.h>
#include <cstdint>

// ---------------------------------------------------------------------------
// Problem constants
// ---------------------------------------------------------------------------
#define BB    4
#define NSEQ  2048
#define MSEQ  512
#define HH    12
#define DD    64
#define DIMV  768
#define TRIPLE 2304
#define BH    (BB*HH)          // 48
#define SCALEF 0.125f
#define TEMPF  24.0f
#define NEGF  (-1e9f)

// Output segment offsets (floats)
#define OUT1_OFF 0
#define OUT2_OFF (BB*NSEQ*DIMV)                 // 6291456
#define OUT3_OFF (OUT2_OFF + BB*MSEQ*DIMV)      // 7864320
#define OUT4_OFF (OUT3_OFF + BB*DIMV)           // 7867392

// ---------------------------------------------------------------------------
// tf32 split + mma.sync helpers (3xTF32 split-precision GEMM)
// ---------------------------------------------------------------------------
__device__ __forceinline__ void tf32_split(float x, uint32_t& hi, uint32_t& lo)
{
    asm("cvt.rna.tf32.f32 %0, %1;" : "=r"(hi) : "f"(x));
    float r = x - __uint_as_float(hi);
    asm("cvt.rna.tf32.f32 %0, %1;" : "=r"(lo) : "f"(r));
}

#define MMA_TF32(d, a0, a1, a2, a3, b0, b1)                                  \
    asm volatile("mma.sync.aligned.m16n8k8.row.col.f32.tf32.tf32.f32 "       \
        "{%0,%1,%2,%3}, {%4,%5,%6,%7}, {%8,%9}, {%0,%1,%2,%3};"              \
        : "+f"(d[0]), "+f"(d[1]), "+f"(d[2]), "+f"(d[3])                     \
        : "r"(a0), "r"(a1), "r"(a2), "r"(a3), "r"(b0), "r"(b1))

// 3 MMAs of the split-precision product into acc
#define MMA3(acc, ahi, alo, bh0, bh1, bl0, bl1)                              \
    do {                                                                     \
        MMA_TF32(acc, ahi[0], ahi[1], ahi[2], ahi[3], bh0, bh1);             \
        MMA_TF32(acc, ahi[0], ahi[1], ahi[2], ahi[3], bl0, bl1);             \
        MMA_TF32(acc, alo[0], alo[1], alo[2], alo[3], bh0, bh1);             \
    } while (0)

// ---------------------------------------------------------------------------
// Device scratch (no cudaMalloc allowed)
// ---------------------------------------------------------------------------
__device__ float g_tq[BB*HH*NSEQ*DD];
__device__ float g_tk[BB*HH*NSEQ*DD];
__device__ float g_tv[BB*HH*NSEQ*DD];
__device__ float g_kq[BB*HH*MSEQ*DD];
__device__ float g_kk[BB*HH*MSEQ*DD];
__device__ float g_kv[BB*HH*MSEQ*DD];
__device__ float g_cq[BB*HH*DD];
__device__ float g_ck[BB*HH*DD];
__device__ float g_cv[BB*HH*DD];
__device__ float g_dots1[BB*HH*NSEQ*MSEQ];   // later overwritten with attn
__device__ float g_dots2[BB*HH*MSEQ*NSEQ];   // later overwritten with k_attn
__device__ float g_attO[BB*NSEQ*DIMV];
__device__ float g_kO[BB*MSEQ*DIMV];
__device__ float g_cO[BB*DIMV];
__device__ float g_mx1[BB*HH*NSEQ];
__device__ float g_s1 [BB*HH*NSEQ];
__device__ float g_sh1[BB*HH*NSEQ];

// ---------------------------------------------------------------------------
// QKV GEMM (3xTF32 tensor cores):
//   C[rows,2304] = A[rows,768] @ W[768,2304], scatter to q/k/v [b,h,s,d]
// 8 warps as 2(M) x 4(N); warp tile 64x32 = 4x4 m16n8 tiles.
// ---------------------------------------------------------------------------
__global__ void __launch_bounds__(256, 2) qkv_gemm(
    const float* __restrict__ A, const float* __restrict__ W,
    float* __restrict__ oq, float* __restrict__ ok2, float* __restrict__ ov,
    int rows, int seq)
{
    __shared__ __align__(16) float As[16][132];
    __shared__ __align__(16) float Bs[16][132];
    int tid = threadIdx.x;
    int rowBase = blockIdx.y * 128;
    int colBase = blockIdx.x * 128;
    int warp = tid >> 5, lane = tid & 31;
    int wm = warp >> 2, wn = warp & 3;
    int g = lane >> 2, tig = lane & 3;

    float acc[4][4][4];
#pragma unroll
    for (int mt = 0; mt < 4; mt++)
#pragma unroll
        for (int nt = 0; nt < 4; nt++)
#pragma unroll
            for (int c = 0; c < 4; c++) acc[mt][nt][c] = 0.f;

    int aRow = tid >> 2, aCol = (tid & 3) << 2;
    int bRow = tid >> 5, bCol = (tid & 31) << 2;

    for (int kk = 0; kk < DIMV; kk += 16) {
#pragma unroll
        for (int it = 0; it < 2; ++it) {
            int r = rowBase + aRow + it * 64;
            float4 v = make_float4(0.f, 0.f, 0.f, 0.f);
            if (r < rows) v = *(const float4*)(A + (size_t)r * DIMV + kk + aCol);
            As[aCol + 0][aRow + it * 64] = v.x;
            As[aCol + 1][aRow + it * 64] = v.y;
            As[aCol + 2][aRow + it * 64] = v.z;
            As[aCol + 3][aRow + it * 64] = v.w;
        }
#pragma unroll
        for (int it = 0; it < 2; ++it) {
            int kr = bRow + it * 8;
            float4 v = *(const float4*)(W + (size_t)(kk + kr) * TRIPLE + colBase + bCol);
            *(float4*)&Bs[kr][bCol] = v;
        }
        __syncthreads();

#pragma unroll
        for (int kc = 0; kc < 2; kc++) {
            int kb = kc * 8;
            uint32_t bhi[4][2], blo[4][2];
#pragma unroll
            for (int nt = 0; nt < 4; nt++) {
                int cb = wn * 32 + nt * 8 + g;
                tf32_split(Bs[kb + tig][cb],     bhi[nt][0], blo[nt][0]);
                tf32_split(Bs[kb + tig + 4][cb], bhi[nt][1], blo[nt][1]);
            }
#pragma unroll
            for (int mt = 0; mt < 4; mt++) {
                int rb = wm * 64 + mt * 16;
                uint32_t ahi[4], alo[4];
                tf32_split(As[kb + tig][rb + g],         ahi[0], alo[0]);
                tf32_split(As[kb + tig][rb + g + 8],     ahi[1], alo[1]);
                tf32_split(As[kb + tig + 4][rb + g],     ahi[2], alo[2]);
                tf32_split(As[kb + tig + 4][rb + g + 8], ahi[3], alo[3]);
#pragma unroll
                for (int nt = 0; nt < 4; nt++)
                    MMA3(acc[mt][nt], ahi, alo, bhi[nt][0], bhi[nt][1], blo[nt][0], blo[nt][1]);
            }
        }
        __syncthreads();
    }

    // scatter epilogue: pairs (c0, c0+1) are even-aligned -> same (part, h)
#pragma unroll
    for (int mt = 0; mt < 4; mt++) {
#pragma unroll
        for (int nt = 0; nt < 4; nt++) {
            int c0 = colBase + wn * 32 + nt * 8 + 2 * tig;
            int part = c0 / DIMV, cc = c0 % DIMV;
            int h = cc >> 6, d = cc & 63;
            float* dst = (part == 0) ? oq : (part == 1) ? ok2 : ov;
#pragma unroll
            for (int half = 0; half < 2; half++) {
                int r = rowBase + wm * 64 + mt * 16 + g + half * 8;
                if (r < rows) {
                    int b = r / seq, s = r % seq;
                    size_t idx = ((size_t)(b * HH + h) * seq + s) * DD + d;
                    float v0 = acc[mt][nt][half * 2 + 0];
                    float v1 = acc[mt][nt][half * 2 + 1];
                    *(float2*)(dst + idx) = make_float2(v0, v1);
                }
            }
        }
    }
}

// ---------------------------------------------------------------------------
// Projection GEMM (3xTF32): out[rows,768] = A[rows,768] @ W[768,768] + bias
// ---------------------------------------------------------------------------
__global__ void __launch_bounds__(256, 2) proj_gemm(
    const float* __restrict__ A, const float* __restrict__ W,
    const float* __restrict__ bias, float* __restrict__ outp, int rows)
{
    __shared__ __align__(16) float As[16][132];
    __shared__ __align__(16) float Bs[16][132];
    int tid = threadIdx.x;
    int rowBase = blockIdx.y * 128;
    int colBase = blockIdx.x * 128;
    int warp = tid >> 5, lane = tid & 31;
    int wm = warp >> 2, wn = warp & 3;
    int g = lane >> 2, tig = lane & 3;

    float acc[4][4][4];
#pragma unroll
    for (int mt = 0; mt < 4; mt++)
#pragma unroll
        for (int nt = 0; nt < 4; nt++)
#pragma unroll
            for (int c = 0; c < 4; c++) acc[mt][nt][c] = 0.f;

    int aRow = tid >> 2, aCol = (tid & 3) << 2;
    int bRow = tid >> 5, bCol = (tid & 31) << 2;

    for (int kk = 0; kk < DIMV; kk += 16) {
#pragma unroll
        for (int it = 0; it < 2; ++it) {
            int r = rowBase + aRow + it * 64;
            float4 v = make_float4(0.f, 0.f, 0.f, 0.f);
            if (r < rows) v = *(const float4*)(A + (size_t)r * DIMV + kk + aCol);
            As[aCol + 0][aRow + it * 64] = v.x;
            As[aCol + 1][aRow + it * 64] = v.y;
            As[aCol + 2][aRow + it * 64] = v.z;
            As[aCol + 3][aRow + it * 64] = v.w;
        }
#pragma unroll
        for (int it = 0; it < 2; ++it) {
            int kr = bRow + it * 8;
            float4 v = *(const float4*)(W + (size_t)(kk + kr) * DIMV + colBase + bCol);
            *(float4*)&Bs[kr][bCol] = v;
        }
        __syncthreads();

#pragma unroll
        for (int kc = 0; kc < 2; kc++) {
            int kb = kc * 8;
            uint32_t bhi[4][2], blo[4][2];
#pragma unroll
            for (int nt = 0; nt < 4; nt++) {
                int cb = wn * 32 + nt * 8 + g;
                tf32_split(Bs[kb + tig][cb],     bhi[nt][0], blo[nt][0]);
                tf32_split(Bs[kb + tig + 4][cb], bhi[nt][1], blo[nt][1]);
            }
#pragma unroll
            for (int mt = 0; mt < 4; mt++) {
                int rb = wm * 64 + mt * 16;
                uint32_t ahi[4], alo[4];
                tf32_split(As[kb + tig][rb + g],         ahi[0], alo[0]);
                tf32_split(As[kb + tig][rb + g + 8],     ahi[1], alo[1]);
                tf32_split(As[kb + tig + 4][rb + g],     ahi[2], alo[2]);
                tf32_split(As[kb + tig + 4][rb + g + 8], ahi[3], alo[3]);
#pragma unroll
                for (int nt = 0; nt < 4; nt++)
                    MMA3(acc[mt][nt], ahi, alo, bhi[nt][0], bhi[nt][1], blo[nt][0], blo[nt][1]);
            }
        }
        __syncthreads();
    }

#pragma unroll
    for (int mt = 0; mt < 4; mt++) {
#pragma unroll
        for (int nt = 0; nt < 4; nt++) {
            int c0 = colBase + wn * 32 + nt * 8 + 2 * tig;
            float b0 = bias[c0], b1 = bias[c0 + 1];
#pragma unroll
            for (int half = 0; half < 2; half++) {
                int r = rowBase + wm * 64 + mt * 16 + g + half * 8;
                if (r < rows) {
                    float v0 = acc[mt][nt][half * 2 + 0] + b0;
                    float v1 = acc[mt][nt][half * 2 + 1] + b1;
                    *(float2*)(outp + (size_t)r * DIMV + c0) = make_float2(v0, v1);
                }
            }
        }
    }
}

// ---------------------------------------------------------------------------
// Batched NT GEMM for dots via 3xTF32 mma.sync (validated R15).
// ---------------------------------------------------------------------------
__global__ void __launch_bounds__(256, 2) dots_gemm(
    const float* __restrict__ Aall, const float* __restrict__ Ball,
    const int* __restrict__ mask, float* __restrict__ outAll,
    int rowsC, int colsC, int mrs, int mcs)
{
    int bh = blockIdx.z;
    const float* A = Aall + (size_t)bh * rowsC * DD;
    const float* Bm = Ball + (size_t)bh * colsC * DD;
    const int* mk = mask + (size_t)bh * NSEQ * MSEQ;
    float* outp = outAll + (size_t)bh * rowsC * colsC;

    __shared__ __align__(16) float As[16][132];
    __shared__ __align__(16) float Bs[16][132];
    int tid = threadIdx.x;
    int rowBase = blockIdx.y * 128;
    int colBase = blockIdx.x * 128;
    int warp = tid >> 5, lane = tid & 31;
    int wm = warp >> 2, wn = warp & 3;
    int g = lane >> 2, tig = lane & 3;

    float acc[4][4][4];
#pragma unroll
    for (int mt = 0; mt < 4; mt++)
#pragma unroll
        for (int nt = 0; nt < 4; nt++)
#pragma unroll
            for (int c = 0; c < 4; c++) acc[mt][nt][c] = 0.f;

    int aRow = tid >> 2, aCol = (tid & 3) << 2;

    for (int kk = 0; kk < DD; kk += 16) {
#pragma unroll
        for (int it = 0; it < 2; ++it) {
            float4 v = *(const float4*)(A + (size_t)(rowBase + aRow + it * 64) * DD + kk + aCol);
            As[aCol + 0][aRow + it * 64] = v.x;
            As[aCol + 1][aRow + it * 64] = v.y;
            As[aCol + 2][aRow + it * 64] = v.z;
            As[aCol + 3][aRow + it * 64] = v.w;
            float4 w = *(const float4*)(Bm + (size_t)(colBase + aRow + it * 64) * DD + kk + aCol);
            Bs[aCol + 0][aRow + it * 64] = w.x;
            Bs[aCol + 1][aRow + it * 64] = w.y;
            Bs[aCol + 2][aRow + it * 64] = w.z;
            Bs[aCol + 3][aRow + it * 64] = w.w;
        }
        __syncthreads();

#pragma unroll
        for (int kc = 0; kc < 2; kc++) {
            int kb = kc * 8;
            uint32_t bhi[4][2], blo[4][2];
#pragma unroll
            for (int nt = 0; nt < 4; nt++) {
                int cb = wn * 32 + nt * 8 + g;
                tf32_split(Bs[kb + tig][cb],     bhi[nt][0], blo[nt][0]);
                tf32_split(Bs[kb + tig + 4][cb], bhi[nt][1], blo[nt][1]);
            }
#pragma unroll
            for (int mt = 0; mt < 4; mt++) {
                int rb = wm * 64 + mt * 16;
                uint32_t ahi[4], alo[4];
                tf32_split(As[kb + tig][rb + g],         ahi[0], alo[0]);
                tf32_split(As[kb + tig][rb + g + 8],     ahi[1], alo[1]);
                tf32_split(As[kb + tig + 4][rb + g],     ahi[2], alo[2]);
                tf32_split(As[kb + tig + 4][rb + g + 8], ahi[3], alo[3]);
#pragma unroll
                for (int nt = 0; nt < 4; nt++)
                    MMA3(acc[mt][nt], ahi, alo, bhi[nt][0], bhi[nt][1], blo[nt][0], blo[nt][1]);
            }
        }
        __syncthreads();
    }

#pragma unroll
    for (int mt = 0; mt < 4; mt++) {
#pragma unroll
        for (int nt = 0; nt < 4; nt++) {
            int r0 = rowBase + wm * 64 + mt * 16 + g;
            int r1 = r0 + 8;
            int c0 = colBase + wn * 32 + nt * 8 + 2 * tig;
            float v0 = acc[mt][nt][0] * SCALEF;
            float v1 = acc[mt][nt][1] * SCALEF;
            float v2 = acc[mt][nt][2] * SCALEF;
            float v3 = acc[mt][nt][3] * SCALEF;
            if (mk[r0 * mrs + c0 * mcs]) v0 = NEGF;
            if (mk[r0 * mrs + (c0 + 1) * mcs]) v1 = NEGF;
            if (mk[r1 * mrs + c0 * mcs]) v2 = NEGF;
            if (mk[r1 * mrs + (c0 + 1) * mcs]) v3 = NEGF;
            *(float2*)(outp + (size_t)r0 * colsC + c0) = make_float2(v0, v1);
            *(float2*)(outp + (size_t)r1 * colsC + c0) = make_float2(v2, v3);
        }
    }
}

// ---------------------------------------------------------------------------
// Batched AV GEMM (3xTF32): C[rowsC,64] = A[rowsC,K] @ V[K,64]
// 8 warps as 4(M) x 2(N); warp tile 32x32 = 2x4 m16n8 tiles.
// ---------------------------------------------------------------------------
__global__ void __launch_bounds__(256, 2) av_gemm(
    const float* __restrict__ Aall, const float* __restrict__ Vall,
    float* __restrict__ outp, int rowsC, int Kdim, int seq)
{
    int bh = blockIdx.y;
    int b = bh / HH, h = bh % HH;
    const float* A = Aall + (size_t)bh * rowsC * Kdim;
    const float* V = Vall + (size_t)bh * Kdim * DD;

    __shared__ __align__(16) float As[16][132];
    __shared__ __align__(16) float Bs[16][68];
    int tid = threadIdx.x;
    int rowBase = blockIdx.x * 128;
    int warp = tid >> 5, lane = tid & 31;
    int wm = warp >> 1, wn = warp & 1;     // 4 x 2 warp grid
    int g = lane >> 2, tig = lane & 3;

    float acc[2][4][4];
#pragma unroll
    for (int mt = 0; mt < 2; mt++)
#pragma unroll
        for (int nt = 0; nt < 4; nt++)
#pragma unroll
            for (int c = 0; c < 4; c++) acc[mt][nt][c] = 0.f;

    int aRow = tid >> 2, aCol = (tid & 3) << 2;
    int vRow = tid >> 4, vCol = (tid & 15) << 2;

    for (int kk = 0; kk < Kdim; kk += 16) {
#pragma unroll
        for (int it = 0; it < 2; ++it) {
            float4 v = *(const float4*)(A + (size_t)(rowBase + aRow + it * 64) * Kdim + kk + aCol);
            As[aCol + 0][aRow + it * 64] = v.x;
            As[aCol + 1][aRow + it * 64] = v.y;
            As[aCol + 2][aRow + it * 64] = v.z;
            As[aCol + 3][aRow + it * 64] = v.w;
        }
        {
            float4 v = *(const float4*)(V + (size_t)(kk + vRow) * DD + vCol);
            *(float4*)&Bs[vRow][vCol] = v;
        }
        __syncthreads();

#pragma unroll
        for (int kc = 0; kc < 2; kc++) {
            int kb = kc * 8;
            uint32_t bhi[4][2], blo[4][2];
#pragma unroll
            for (int nt = 0; nt < 4; nt++) {
                int cb = wn * 32 + nt * 8 + g;
                tf32_split(Bs[kb + tig][cb],     bhi[nt][0], blo[nt][0]);
                tf32_split(Bs[kb + tig + 4][cb], bhi[nt][1], blo[nt][1]);
            }
#pragma unroll
            for (int mt = 0; mt < 2; mt++) {
                int rb = wm * 32 + mt * 16;
                uint32_t ahi[4], alo[4];
                tf32_split(As[kb + tig][rb + g],         ahi[0], alo[0]);
                tf32_split(As[kb + tig][rb + g + 8],     ahi[1], alo[1]);
                tf32_split(As[kb + tig + 4][rb + g],     ahi[2], alo[2]);
                tf32_split(As[kb + tig + 4][rb + g + 8], ahi[3], alo[3]);
#pragma unroll
                for (int nt = 0; nt < 4; nt++)
                    MMA3(acc[mt][nt], ahi, alo, bhi[nt][0], bhi[nt][1], blo[nt][0], blo[nt][1]);
            }
        }
        __syncthreads();
    }

#pragma unroll
    for (int mt = 0; mt < 2; mt++) {
#pragma unroll
        for (int nt = 0; nt < 4; nt++) {
            int d0 = wn * 32 + nt * 8 + 2 * tig;
#pragma unroll
            for (int half = 0; half < 2; half++) {
                int r = rowBase + wm * 32 + mt * 16 + g + half * 8;
                float v0 = acc[mt][nt][half * 2 + 0];
                float v1 = acc[mt][nt][half * 2 + 1];
                *(float2*)(outp + (size_t)(b * seq + r) * DIMV + h * 64 + d0) = make_float2(v0, v1);
            }
        }
    }
}

// ---------------------------------------------------------------------------
// Softmax stats, branch 1: per row (length 512): max, sum exp, sum exp(24*)
// ---------------------------------------------------------------------------
__global__ void __launch_bounds__(256) stats1_kernel()
{
    int gw = (blockIdx.x * 256 + threadIdx.x) >> 5;
    int lane = threadIdx.x & 31;
    const float* row = g_dots1 + (size_t)gw * MSEQ;
    float v[16], m = -3.4e38f;
#pragma unroll
    for (int i = 0; i < 16; i++) { v[i] = row[lane + 32 * i]; m = fmaxf(m, v[i]); }
#pragma unroll
    for (int o = 16; o > 0; o >>= 1) m = fmaxf(m, __shfl_xor_sync(0xffffffffu, m, o));
    float s = 0.f, sh = 0.f;
#pragma unroll
    for (int i = 0; i < 16; i++) {
        float t = v[i] - m;
        s += __expf(t);
        sh += __expf(TEMPF * t);
    }
#pragma unroll
    for (int o = 16; o > 0; o >>= 1) {
        s  += __shfl_xor_sync(0xffffffffu, s, o);
        sh += __shfl_xor_sync(0xffffffffu, sh, o);
    }
    if (lane == 0) { g_mx1[gw] = m; g_s1[gw] = s; g_sh1[gw] = sh; }
}

// ---------------------------------------------------------------------------
// Branch-1 apply: 32x32 tile transpose.
// ---------------------------------------------------------------------------
__global__ void apply1_kernel(const float* __restrict__ krd, float* __restrict__ out4)
{
    __shared__ float sd[32][33];
    __shared__ float sk[32][33];
    __shared__ float smx[32], ss1[32], ssh[32];
    int bh = blockIdx.z;
    int n0 = blockIdx.x * 32, m0 = blockIdx.y * 32;
    int tx = threadIdx.x, ty = threadIdx.y;
    const float* dbase = g_dots1 + (size_t)bh * NSEQ * MSEQ;
    const float* kbase = krd + (size_t)bh * MSEQ * NSEQ;

    int t = ty * 32 + tx;
    if (t < 32) {
        smx[t] = g_mx1[bh * NSEQ + n0 + t];
        ss1[t] = g_s1 [bh * NSEQ + n0 + t];
        ssh[t] = g_sh1[bh * NSEQ + n0 + t];
    }
#pragma unroll
    for (int it = 0; it < 4; it++) {
        int l = ty + 8 * it;
        sd[l][tx] = dbase[(size_t)(n0 + l) * MSEQ + m0 + tx];
        sk[l][tx] = kbase[(size_t)(m0 + l) * NSEQ + n0 + tx];
    }
    __syncthreads();

#pragma unroll
    for (int it = 0; it < 4; it++) {
        int nl = ty + 8 * it;
        float e = __expf(sd[nl][tx] - smx[nl]);
        float a = e / ss1[nl] * sk[tx][nl];
        g_dots1[(size_t)bh * NSEQ * MSEQ + (size_t)(n0 + nl) * MSEQ + m0 + tx] = a;
    }
#pragma unroll
    for (int it = 0; it < 4; it++) {
        int ml = ty + 8 * it;
        float e = __expf(TEMPF * (sd[tx][ml] - smx[tx]));
        float hv = e / ssh[tx] * sk[ml][tx];
        out4[(size_t)bh * MSEQ * NSEQ + (size_t)(m0 + ml) * NSEQ + n0 + tx] = hv;
    }
}

// ---------------------------------------------------------------------------
// Branch-2 fused softmax + krd apply: one block per row (length 2048)
// ---------------------------------------------------------------------------
__global__ void __launch_bounds__(256) softmax2_kernel(const float* __restrict__ krd)
{
    __shared__ float red[8];
    int row = blockIdx.x;
    int tid = threadIdx.x;
    int lane = tid & 31, warp = tid >> 5;
    float* drow = g_dots2 + (size_t)row * NSEQ;
    const float* krow = krd + (size_t)row * NSEQ;

    float4 v0 = ((const float4*)drow)[tid];
    float4 v1 = ((const float4*)drow)[tid + 256];
    float m = fmaxf(fmaxf(fmaxf(v0.x, v0.y), fmaxf(v0.z, v0.w)),
                    fmaxf(fmaxf(v1.x, v1.y), fmaxf(v1.z, v1.w)));
#pragma unroll
    for (int o = 16; o > 0; o >>= 1) m = fmaxf(m, __shfl_xor_sync(0xffffffffu, m, o));
    if (lane == 0) red[warp] = m;
    __syncthreads();
    m = red[lane & 7];
#pragma unroll
    for (int o = 4; o > 0; o >>= 1) m = fmaxf(m, __shfl_xor_sync(0xffffffffu, m, o));

    float e0x = __expf(v0.x - m), e0y = __expf(v0.y - m), e0z = __expf(v0.z - m), e0w = __expf(v0.w - m);
    float e1x = __expf(v1.x - m), e1y = __expf(v1.y - m), e1z = __expf(v1.z - m), e1w = __expf(v1.w - m);
    float s = e0x + e0y + e0z + e0w + e1x + e1y + e1z + e1w;
#pragma unroll
    for (int o = 16; o > 0; o >>= 1) s += __shfl_xor_sync(0xffffffffu, s, o);
    __syncthreads();
    if (lane == 0) red[warp] = s;
    __syncthreads();
    s = red[lane & 7];
#pragma unroll
    for (int o = 4; o > 0; o >>= 1) s += __shfl_xor_sync(0xffffffffu, s, o);
    float inv = 1.f / s;

    float4 k0 = ((const float4*)krow)[tid];
    float4 k1 = ((const float4*)krow)[tid + 256];
    float4 o0 = make_float4(e0x * inv * k0.x, e0y * inv * k0.y, e0z * inv * k0.z, e0w * inv * k0.w);
    float4 o1 = make_float4(e1x * inv * k1.x, e1y * inv * k1.y, e1z * inv * k1.z, e1w * inv * k1.w);
    ((float4*)drow)[tid] = o0;
    ((float4*)drow)[tid + 256] = o1;
}

// ---------------------------------------------------------------------------
// Branch 3: cluster query vs kernel keys. One block per (b,h).
// ---------------------------------------------------------------------------
__global__ void __launch_bounds__(256) cluster_kernel(const int* __restrict__ mask)
{
    int bh = blockIdx.x;
    int b = bh / HH, h = bh % HH;
    __shared__ float q[64];
    __shared__ float p[512];
    __shared__ float red[256];
    int tid = threadIdx.x;
    const float* cq = g_cq + bh * 64;
    const float* kk = g_kk + (size_t)bh * MSEQ * DD;
    const float* kv = g_kv + (size_t)bh * MSEQ * DD;

    if (tid < 64) q[tid] = cq[tid];
    __syncthreads();

    for (int m = tid; m < MSEQ; m += 256) {
        float acc = 0.f;
#pragma unroll
        for (int d = 0; d < 64; d++) acc += q[d] * kk[m * 64 + d];
        acc *= SCALEF;
        if (mask[(size_t)bh * NSEQ * MSEQ + m]) acc = NEGF;
        p[m] = acc;
    }
    __syncthreads();

    red[tid] = fmaxf(p[tid], p[tid + 256]);
    __syncthreads();
    for (int s = 128; s > 0; s >>= 1) {
        if (tid < s) red[tid] = fmaxf(red[tid], red[tid + s]);
        __syncthreads();
    }
    float mx = red[0];
    __syncthreads();

    float e0 = __expf(p[tid] - mx), e1 = __expf(p[tid + 256] - mx);
    p[tid] = e0; p[tid + 256] = e1;
    red[tid] = e0 + e1;
    __syncthreads();
    for (int s = 128; s > 0; s >>= 1) {
        if (tid < s) red[tid] += red[tid + s];
        __syncthreads();
    }
    float inv = 1.f / red[0];
    __syncthreads();

    int d = tid & 63, part = tid >> 6;
    float acc = 0.f;
    for (int m = part * 128; m < part * 128 + 128; m++) acc += p[m] * kv[m * 64 + d];
    red[tid] = acc * inv;
    __syncthreads();
    if (part == 0)
        g_cO[b * DIMV + h * 64 + d] = red[d] + red[64 + d] + red[128 + d] + red[192 + d];
}

// ---------------------------------------------------------------------------
// Host launcher
// ---------------------------------------------------------------------------
extern "C" void kernel_launch(void* const* d_in, const int* in_sizes, int n_in,
                              void* d_out, int out_size)
{
    const float* x    = (const float*)d_in[0];
    const float* kx   = (const float*)d_in[1];
    const float* krd  = (const float*)d_in[2];
    const float* clst = (const float*)d_in[3];
    const int*   mask = (const int*)d_in[4];
    const float* Wqkv = (const float*)d_in[5];
    const float* Wout = (const float*)d_in[6];
    const float* bout = (const float*)d_in[7];
    float* out  = (float*)d_out;
    float* out1 = out + OUT1_OFF;
    float* out2 = out + OUT2_OFF;
    float* out3 = out + OUT3_OFF;
    float* out4 = out + OUT4_OFF;

    float *p_tq, *p_tk, *p_tv, *p_kq, *p_kk, *p_kv, *p_cq, *p_ck, *p_cv;
    float *p_d1, *p_d2, *p_attO, *p_kO, *p_cO;
    cudaGetSymbolAddress((void**)&p_tq, g_tq);
    cudaGetSymbolAddress((void**)&p_tk, g_tk);
    cudaGetSymbolAddress((void**)&p_tv, g_tv);
    cudaGetSymbolAddress((void**)&p_kq, g_kq);
    cudaGetSymbolAddress((void**)&p_kk, g_kk);
    cudaGetSymbolAddress((void**)&p_kv, g_kv);
    cudaGetSymbolAddress((void**)&p_cq, g_cq);
    cudaGetSymbolAddress((void**)&p_ck, g_ck);
    cudaGetSymbolAddress((void**)&p_cv, g_cv);
    cudaGetSymbolAddress((void**)&p_d1, g_dots1);
    cudaGetSymbolAddress((void**)&p_d2, g_dots2);
    cudaGetSymbolAddress((void**)&p_attO, g_attO);
    cudaGetSymbolAddress((void**)&p_kO, g_kO);
    cudaGetSymbolAddress((void**)&p_cO, g_cO);

    // 1) QKV projections (tf32x3)
    qkv_gemm<<<dim3(TRIPLE / 128, (BB * NSEQ) / 128), 256>>>(x, Wqkv, p_tq, p_tk, p_tv, BB * NSEQ, NSEQ);
    qkv_gemm<<<dim3(TRIPLE / 128, (BB * MSEQ) / 128), 256>>>(kx, Wqkv, p_kq, p_kk, p_kv, BB * MSEQ, MSEQ);
    qkv_gemm<<<dim3(TRIPLE / 128, 1), 256>>>(clst, Wqkv, p_cq, p_ck, p_cv, BB, 1);

    // 2) dots (masked + scaled, tf32x3)
    dots_gemm<<<dim3(MSEQ / 128, NSEQ / 128, BH), 256>>>(p_tq, p_kk, mask, p_d1,
                                                         NSEQ, MSEQ, MSEQ, 1);
    dots_gemm<<<dim3(NSEQ / 128, MSEQ / 128, BH), 256>>>(p_kq, p_tk, mask, p_d2,
                                                         MSEQ, NSEQ, 1, MSEQ);

    // 3) softmax stats (branch 1) + fused softmax (branch 2)
    stats1_kernel<<<(BH * NSEQ) / 8, 256>>>();
    softmax2_kernel<<<BH * MSEQ, 256>>>(krd);

    // 4) branch-1 apply (attn / attn_hot)
    apply1_kernel<<<dim3(NSEQ / 32, MSEQ / 32, BH), dim3(32, 8)>>>(krd, out4);

    // 5) attention-value GEMMs (tf32x3)
    av_gemm<<<dim3(NSEQ / 128, BH), 256>>>(p_d1, p_kv, p_attO, NSEQ, MSEQ, NSEQ);
    av_gemm<<<dim3(MSEQ / 128, BH), 256>>>(p_d2, p_tv, p_kO, MSEQ, NSEQ, MSEQ);

    // 6) cluster branch
    cluster_kernel<<<BH, 256>>>(mask);

    // 7) output projections (tf32x3)
    proj_gemm<<<dim3(DIMV / 128, (BB * NSEQ) / 128), 256>>>(p_attO, Wout, bout, out1, BB * NSEQ);
    proj_gemm<<<dim3(DIMV / 128, (BB * MSEQ) / 128), 256>>>(p_kO, Wout, bout, out2, BB * MSEQ);
    proj_gemm<<<dim3(DIMV / 128, 1), 256>>>(p_cO, Wout, bout, out3, BB);
}